// round 6
// baseline (speedup 1.0000x reference)
#include <cuda_runtime.h>
#include <cuda_bf16.h>
#include <math.h>
#include <stdint.h>

// Shapes: B=1, S=128, L=256, D=768 (H=12, dh=64), M = S*L = 32768, 3D = 2304.
#define SQ   128
#define LQ   256
#define DQ   768
#define HQ   12
#define DHQ  64
#define MQ   (SQ * LQ)      // 32768
#define N3Q  (3 * DQ)       // 2304

// ---------------- scratch (no cudaMalloc allowed) ----------------
__device__ float g_qkv[(size_t)MQ * N3Q];       // 302 MB, reused for row & col stage
__device__ float g_attn[HQ * LQ * LQ];          // 3 MB   row-attention logits/probs
__device__ float g_tmp[(size_t)MQ * DQ];        // 100 MB attention outputs (row then col)
__device__ float g_out1[(size_t)MQ * DQ];       // 100 MB output of first residual+LN

// ================= helpers ==================
__device__ __forceinline__ float tf32r(float x) {
    uint32_t u;
    asm("cvt.rna.tf32.f32 %0, %1;" : "=r"(u) : "f"(x));
    return __uint_as_float(u);
}

__device__ __forceinline__ void mma_tf32_16x8x8(float* c, const uint32_t* a, const uint32_t* b) {
    asm volatile(
        "mma.sync.aligned.m16n8k8.row.col.f32.tf32.tf32.f32 "
        "{%0,%1,%2,%3}, {%4,%5,%6,%7}, {%8,%9}, {%0,%1,%2,%3};"
        : "+f"(c[0]), "+f"(c[1]), "+f"(c[2]), "+f"(c[3])
        : "r"(a[0]), "r"(a[1]), "r"(a[2]), "r"(a[3]), "r"(b[0]), "r"(b[1]));
}

// =================================================================
// Kernel 1: C[M,2304] = A[M,768] * B[2304,768]^T + bias
// mma.sync tf32 x3 split. Tile 128x128, K-chunk 16, 8 warps (4m x 2n).
// smem rows padded to 20 words -> conflict-free fragment loads.
// =================================================================
__global__ __launch_bounds__(256) void qkv_gemm_mma(
    const float* __restrict__ A, const float* __restrict__ Bm,
    const float* __restrict__ bias, float* __restrict__ C)
{
    __shared__ uint32_t Ah[128][20], Al[128][20], Bh[128][20], Bl[128][20];

    const int tid = threadIdx.x;
    const int m0 = blockIdx.y * 128;
    const int n0 = blockIdx.x * 128;
    const int lr = tid >> 2;           // 0..63
    const int lc = (tid & 3) << 2;     // 0,4,8,12
    const int w  = tid >> 5;
    const int l  = tid & 31;
    const int g  = l >> 2;             // 0..7
    const int q  = l & 3;              // 0..3
    const int wm = (w & 3) * 32;
    const int wn = (w >> 2) * 64;

    const float* Ap = A  + (size_t)(m0 + lr) * DQ + lc;
    const float* Bp = Bm + (size_t)(n0 + lr) * DQ + lc;

    float4 ra0 = *(const float4*)Ap;
    float4 ra1 = *(const float4*)(Ap + (size_t)64 * DQ);
    float4 rb0 = *(const float4*)Bp;
    float4 rb1 = *(const float4*)(Bp + (size_t)64 * DQ);

    float c[2][8][4];
#pragma unroll
    for (int mi = 0; mi < 2; mi++)
#pragma unroll
        for (int ni = 0; ni < 8; ni++)
#pragma unroll
            for (int t = 0; t < 4; t++) c[mi][ni][t] = 0.f;

    const int NCH = DQ / 16;   // 48
    for (int ch = 0; ch < NCH; ch++) {
        // ---- split + store staged regs to smem ----
        {
            float h, lo;
#pragma unroll
            for (int t = 0; t < 4; t++) {
                float v = (&ra0.x)[t];
                h = tf32r(v); lo = tf32r(v - h);
                Ah[lr][lc + t] = __float_as_uint(h);
                Al[lr][lc + t] = __float_as_uint(lo);
                v = (&ra1.x)[t];
                h = tf32r(v); lo = tf32r(v - h);
                Ah[lr + 64][lc + t] = __float_as_uint(h);
                Al[lr + 64][lc + t] = __float_as_uint(lo);
                v = (&rb0.x)[t];
                h = tf32r(v); lo = tf32r(v - h);
                Bh[lr][lc + t] = __float_as_uint(h);
                Bl[lr][lc + t] = __float_as_uint(lo);
                v = (&rb1.x)[t];
                h = tf32r(v); lo = tf32r(v - h);
                Bh[lr + 64][lc + t] = __float_as_uint(h);
                Bl[lr + 64][lc + t] = __float_as_uint(lo);
            }
        }
        __syncthreads();

        if (ch + 1 < NCH) {
            Ap += 16; Bp += 16;
            ra0 = *(const float4*)Ap;
            ra1 = *(const float4*)(Ap + (size_t)64 * DQ);
            rb0 = *(const float4*)Bp;
            rb1 = *(const float4*)(Bp + (size_t)64 * DQ);
        }

#pragma unroll
        for (int k0 = 0; k0 < 16; k0 += 8) {
            uint32_t ah[2][4], al[2][4], bh[8][2], bl[8][2];
#pragma unroll
            for (int mi = 0; mi < 2; mi++) {
                int r = wm + mi * 16 + g;
                ah[mi][0] = Ah[r][k0 + q];       ah[mi][1] = Ah[r + 8][k0 + q];
                ah[mi][2] = Ah[r][k0 + q + 4];   ah[mi][3] = Ah[r + 8][k0 + q + 4];
                al[mi][0] = Al[r][k0 + q];       al[mi][1] = Al[r + 8][k0 + q];
                al[mi][2] = Al[r][k0 + q + 4];   al[mi][3] = Al[r + 8][k0 + q + 4];
            }
#pragma unroll
            for (int ni = 0; ni < 8; ni++) {
                int rn = wn + ni * 8 + g;
                bh[ni][0] = Bh[rn][k0 + q];  bh[ni][1] = Bh[rn][k0 + q + 4];
                bl[ni][0] = Bl[rn][k0 + q];  bl[ni][1] = Bl[rn][k0 + q + 4];
            }
#pragma unroll
            for (int mi = 0; mi < 2; mi++)
#pragma unroll
                for (int ni = 0; ni < 8; ni++) {
                    mma_tf32_16x8x8(c[mi][ni], ah[mi], bh[ni]);
                    mma_tf32_16x8x8(c[mi][ni], ah[mi], bl[ni]);
                    mma_tf32_16x8x8(c[mi][ni], al[mi], bh[ni]);
                }
        }
        __syncthreads();
    }

    // ---- epilogue: bias + store ----
#pragma unroll
    for (int ni = 0; ni < 8; ni++) {
        const int col = n0 + wn + ni * 8 + 2 * q;
        const float2 bv = *(const float2*)(bias + col);
#pragma unroll
        for (int mi = 0; mi < 2; mi++) {
            const int row0 = m0 + wm + mi * 16 + g;
            float2 o0 = make_float2(c[mi][ni][0] + bv.x, c[mi][ni][1] + bv.y);
            float2 o1 = make_float2(c[mi][ni][2] + bv.x, c[mi][ni][3] + bv.y);
            *(float2*)(C + (size_t)row0 * N3Q + col)       = o0;
            *(float2*)(C + (size_t)(row0 + 8) * N3Q + col) = o1;
        }
    }
}

// =================================================================
// Kernel 2: row logits   attn[h,i,j] = sum_{s,c} Q[s,i,h,c] K[s,j,h,c]
// =================================================================
__global__ __launch_bounds__(256) void row_logits(
    const float* __restrict__ qkv, float* __restrict__ attn)
{
    __shared__ float Qs[64][65];
    __shared__ float Ks[64][65];
    const int h  = blockIdx.z;
    const int i0 = blockIdx.y * 64;
    const int j0 = blockIdx.x * 64;
    const int tid  = threadIdx.x;
    const int lrow = tid >> 2;
    const int lcol = (tid & 3) << 4;
    const int tx = tid & 15;
    const int ty = tid >> 4;
    const int hb = h * DHQ;

    float acc[4][4];
#pragma unroll
    for (int i = 0; i < 4; i++)
#pragma unroll
        for (int j = 0; j < 4; j++) acc[i][j] = 0.f;

    for (int s = 0; s < SQ; s++) {
        const float* qrow = qkv + (size_t)(s * LQ + i0 + lrow) * N3Q + hb + lcol;
        const float* krow = qkv + (size_t)(s * LQ + j0 + lrow) * N3Q + DQ + hb + lcol;
#pragma unroll
        for (int u = 0; u < 16; u += 4) {
            float4 qa = *(const float4*)(qrow + u);
            Qs[lrow][lcol + u + 0] = qa.x; Qs[lrow][lcol + u + 1] = qa.y;
            Qs[lrow][lcol + u + 2] = qa.z; Qs[lrow][lcol + u + 3] = qa.w;
            float4 ka = *(const float4*)(krow + u);
            Ks[lrow][lcol + u + 0] = ka.x; Ks[lrow][lcol + u + 1] = ka.y;
            Ks[lrow][lcol + u + 2] = ka.z; Ks[lrow][lcol + u + 3] = ka.w;
        }
        __syncthreads();
#pragma unroll 16
        for (int cix = 0; cix < DHQ; cix++) {
            float a[4], b[4];
#pragma unroll
            for (int r = 0; r < 4; r++) a[r] = Qs[ty * 4 + r][cix];
#pragma unroll
            for (int r = 0; r < 4; r++) b[r] = Ks[tx * 4 + r][cix];
#pragma unroll
            for (int i = 0; i < 4; i++)
#pragma unroll
                for (int j = 0; j < 4; j++)
                    acc[i][j] += a[i] * b[j];
        }
        __syncthreads();
    }
#pragma unroll
    for (int i = 0; i < 4; i++) {
        float4 v = make_float4(acc[i][0], acc[i][1], acc[i][2], acc[i][3]);
        *(float4*)&attn[(size_t)h * LQ * LQ + (i0 + ty * 4 + i) * LQ + j0 + tx * 4] = v;
    }
}

// =================================================================
// Kernel 3: softmax over last dim (256) of attn[h,i,:]
// =================================================================
__global__ __launch_bounds__(256) void softmax_row(float* __restrict__ attn)
{
    const int row = blockIdx.x;
    float* p = attn + (size_t)row * LQ;
    const int t = threadIdx.x;
    float v = p[t];

    __shared__ float red[8];
    float m = v;
#pragma unroll
    for (int o = 16; o > 0; o >>= 1) m = fmaxf(m, __shfl_xor_sync(0xffffffffu, m, o));
    if ((t & 31) == 0) red[t >> 5] = m;
    __syncthreads();
    float mm = red[0];
#pragma unroll
    for (int k = 1; k < 8; k++) mm = fmaxf(mm, red[k]);
    __syncthreads();

    float e = expf(v - mm);
    float s = e;
#pragma unroll
    for (int o = 16; o > 0; o >>= 1) s += __shfl_xor_sync(0xffffffffu, s, o);
    if ((t & 31) == 0) red[t >> 5] = s;
    __syncthreads();
    float tot = 0.f;
#pragma unroll
    for (int k = 0; k < 8; k++) tot += red[k];

    p[t] = e / tot;
}

// =================================================================
// Kernel 4: row AV  out[s,i,h,d] = sum_j attn[h,i,j] V[s,j,h,d]
// =================================================================
__global__ __launch_bounds__(256) void row_av(
    const float* __restrict__ attn, const float* __restrict__ qkv,
    float* __restrict__ out)
{
    __shared__ float As[64][36];
    __shared__ float Vs[32][68];
    const int i0 = blockIdx.x * 64;
    const int h  = blockIdx.y;
    const int s  = blockIdx.z;
    const int tid = threadIdx.x;
    const int tx = tid & 15, ty = tid >> 4;
    const int a_row = tid >> 2, a_col = (tid & 3) << 3;
    const int v_row = tid >> 3, v_col = (tid & 7) << 3;

    float acc[4][4];
#pragma unroll
    for (int i = 0; i < 4; i++)
#pragma unroll
        for (int j = 0; j < 4; j++) acc[i][j] = 0.f;

    for (int jb = 0; jb < LQ; jb += 32) {
        const float* ap = attn + (size_t)h * LQ * LQ + (i0 + a_row) * LQ + jb + a_col;
        *(float4*)&As[a_row][a_col]     = *(const float4*)ap;
        *(float4*)&As[a_row][a_col + 4] = *(const float4*)(ap + 4);
        const float* vp = qkv + (size_t)(s * LQ + jb + v_row) * N3Q + 2 * DQ + h * DHQ + v_col;
        *(float4*)&Vs[v_row][v_col]     = *(const float4*)vp;
        *(float4*)&Vs[v_row][v_col + 4] = *(const float4*)(vp + 4);
        __syncthreads();
#pragma unroll 16
        for (int j = 0; j < 32; j++) {
            float a[4], v[4];
#pragma unroll
            for (int r = 0; r < 4; r++) a[r] = As[ty * 4 + r][j];
#pragma unroll
            for (int r = 0; r < 4; r++) v[r] = Vs[j][tx * 4 + r];
#pragma unroll
            for (int i = 0; i < 4; i++)
#pragma unroll
                for (int d = 0; d < 4; d++)
                    acc[i][d] += a[i] * v[d];
        }
        __syncthreads();
    }
#pragma unroll
    for (int i = 0; i < 4; i++) {
        float4 v = make_float4(acc[i][0], acc[i][1], acc[i][2], acc[i][3]);
        *(float4*)&out[(size_t)(s * LQ + i0 + ty * 4 + i) * DQ + h * DHQ + tx * 4] = v;
    }
}

// =================================================================
// Kernel 5: out[row,:] = LN(X[row,:] + R[row,:]) * g + b   (D=768)
// =================================================================
__global__ __launch_bounds__(256) void add_ln(
    const float* __restrict__ X, const float* __restrict__ R,
    const float* __restrict__ g, const float* __restrict__ b,
    float* __restrict__ out)
{
    const int row = blockIdx.x;
    const int t = threadIdx.x;
    const float* x = X + (size_t)row * DQ;
    const float* r = R + (size_t)row * DQ;
    float y0 = x[t]       + r[t];
    float y1 = x[t + 256] + r[t + 256];
    float y2 = x[t + 512] + r[t + 512];
    float s = y0 + y1 + y2;
    float qv = y0 * y0 + y1 * y1 + y2 * y2;

    __shared__ float ss[8], qq[8];
#pragma unroll
    for (int o = 16; o > 0; o >>= 1) {
        s  += __shfl_xor_sync(0xffffffffu, s, o);
        qv += __shfl_xor_sync(0xffffffffu, qv, o);
    }
    if ((t & 31) == 0) { ss[t >> 5] = s; qq[t >> 5] = qv; }
    __syncthreads();
    if (t < 32) {
        float s2 = (t < 8) ? ss[t] : 0.f;
        float q2 = (t < 8) ? qq[t] : 0.f;
#pragma unroll
        for (int o = 4; o > 0; o >>= 1) {
            s2 += __shfl_xor_sync(0xffffffffu, s2, o);
            q2 += __shfl_xor_sync(0xffffffffu, q2, o);
        }
        if (t == 0) { ss[0] = s2; qq[0] = q2; }
    }
    __syncthreads();
    const float invD = 1.f / (float)DQ;
    float mean = ss[0] * invD;
    float var  = qq[0] * invD - mean * mean;
    float inv  = rsqrtf(var + 1e-5f);
    float* o = out + (size_t)row * DQ;
    o[t]       = (y0 - mean) * inv * g[t]       + b[t];
    o[t + 256] = (y1 - mean) * inv * g[t + 256] + b[t + 256];
    o[t + 512] = (y2 - mean) * inv * g[t + 512] + b[t + 512];
}

// =================================================================
// Kernel 7: column attention. One CTA per (l,h); 128 threads; thread i
// owns query i. S=128, dh=64.
// =================================================================
__global__ __launch_bounds__(128) void col_attn_kernel(
    const float* __restrict__ qkv, float* __restrict__ out)
{
    extern __shared__ float sm[];
    float* P  = sm;                 // [128*128] transposed: P[j*128 + i]
    float* Kt = sm + 128 * 128;     // [64*128]
    float* Vt = Kt + 64 * 128;      // [64*128]

    const int l = blockIdx.x;
    const int h = blockIdx.y;
    const int t = threadIdx.x;
    const int base = l * N3Q + h * DHQ;

    const float* krow = qkv + (size_t)(t * LQ) * N3Q + base + DQ;
    const float* vrow = krow + DQ;
#pragma unroll
    for (int c = 0; c < DHQ; c += 4) {
        float4 kv = *(const float4*)(krow + c);
        Kt[(c + 0) * 128 + t] = kv.x; Kt[(c + 1) * 128 + t] = kv.y;
        Kt[(c + 2) * 128 + t] = kv.z; Kt[(c + 3) * 128 + t] = kv.w;
        float4 vv = *(const float4*)(vrow + c);
        Vt[(c + 0) * 128 + t] = vv.x; Vt[(c + 1) * 128 + t] = vv.y;
        Vt[(c + 2) * 128 + t] = vv.z; Vt[(c + 3) * 128 + t] = vv.w;
    }
    float q[DHQ];
    const float* qrow = qkv + (size_t)(t * LQ) * N3Q + base;
#pragma unroll
    for (int c = 0; c < DHQ; c += 4) {
        float4 qv = *(const float4*)(qrow + c);
        q[c] = qv.x; q[c + 1] = qv.y; q[c + 2] = qv.z; q[c + 3] = qv.w;
    }
    __syncthreads();

    for (int j = 0; j < SQ; j++) {
        float a0 = 0.f, a1 = 0.f, a2 = 0.f, a3 = 0.f;
#pragma unroll
        for (int c = 0; c < DHQ; c += 4) {
            a0 += q[c]     * Kt[(c)     * 128 + j];
            a1 += q[c + 1] * Kt[(c + 1) * 128 + j];
            a2 += q[c + 2] * Kt[(c + 2) * 128 + j];
            a3 += q[c + 3] * Kt[(c + 3) * 128 + j];
        }
        P[j * 128 + t] = (a0 + a1) + (a2 + a3);
    }

    float m = -3.4e38f;
    for (int j = 0; j < SQ; j++) m = fmaxf(m, P[j * 128 + t]);
    float ssum = 0.f;
    for (int j = 0; j < SQ; j++) {
        float e = expf(P[j * 128 + t] - m);
        P[j * 128 + t] = e;
        ssum += e;
    }
    const float inv = 1.f / ssum;

    float o[DHQ];
#pragma unroll
    for (int d = 0; d < DHQ; d++) o[d] = 0.f;
    for (int j = 0; j < SQ; j++) {
        float p = P[j * 128 + t];
#pragma unroll
        for (int d = 0; d < DHQ; d++) o[d] += p * Vt[d * 128 + j];
    }

    float* orow = out + (size_t)(t * LQ + l) * DQ + h * DHQ;
#pragma unroll
    for (int d = 0; d < DHQ; d += 4) {
        float4 v = make_float4(o[d] * inv, o[d + 1] * inv, o[d + 2] * inv, o[d + 3] * inv);
        *(float4*)(orow + d) = v;
    }
}

// =================================================================
extern "C" void kernel_launch(void* const* d_in, const int* in_sizes, int n_in,
                              void* d_out, int out_size)
{
    const float* x     = (const float*)d_in[0];
    const float* w_row = (const float*)d_in[1];
    const float* b_row = (const float*)d_in[2];
    const float* w_col = (const float*)d_in[3];
    const float* b_col = (const float*)d_in[4];
    const float* g1    = (const float*)d_in[5];
    const float* beta1 = (const float*)d_in[6];
    const float* g2    = (const float*)d_in[7];
    const float* beta2 = (const float*)d_in[8];
    float* out = (float*)d_out;

    float *qkv, *attn, *tmp, *out1;
    cudaGetSymbolAddress((void**)&qkv,  g_qkv);
    cudaGetSymbolAddress((void**)&attn, g_attn);
    cudaGetSymbolAddress((void**)&tmp,  g_tmp);
    cudaGetSymbolAddress((void**)&out1, g_out1);

    cudaFuncSetAttribute(col_attn_kernel,
                         cudaFuncAttributeMaxDynamicSharedMemorySize, 131072);

    dim3 gemm_grid(N3Q / 128, MQ / 128);   // (18, 256)

    // --- row stage ---
    qkv_gemm_mma<<<gemm_grid, 256>>>(x, w_row, b_row, qkv);
    row_logits<<<dim3(4, 4, HQ), 256>>>(qkv, attn);
    softmax_row<<<HQ * LQ, 256>>>(attn);
    row_av<<<dim3(4, HQ, SQ), 256>>>(attn, qkv, tmp);
    add_ln<<<MQ, 256>>>(x, tmp, g1, beta1, out1);

    // --- column stage ---
    qkv_gemm_mma<<<gemm_grid, 256>>>(out1, w_col, b_col, qkv);
    col_attn_kernel<<<dim3(LQ, HQ), 128, 131072>>>(qkv, tmp);
    add_ln<<<MQ, 256>>>(out1, tmp, g2, beta2, out);
}

// round 8
// speedup vs baseline: 1.1327x; 1.1327x over previous
#include <cuda_runtime.h>
#include <cuda_bf16.h>
#include <math.h>
#include <stdint.h>

// Shapes: B=1, S=128, L=256, D=768 (H=12, dh=64), M = S*L = 32768, 3D = 2304.
#define SQ   128
#define LQ   256
#define DQ   768
#define HQ   12
#define DHQ  64
#define MQ   (SQ * LQ)      // 32768
#define N3Q  (3 * DQ)       // 2304

// ---------------- scratch (no cudaMalloc allowed) ----------------
__device__ float g_qkv[(size_t)MQ * N3Q];        // 302 MB
__device__ float g_attn[HQ * LQ * LQ];           // 3 MB
__device__ float g_tmp[(size_t)MQ * DQ];         // 100 MB (Ahi during row GEMM, then row/col attn out)
__device__ float g_out1[(size_t)MQ * DQ];        // 100 MB (Alo during row GEMM, then LN1 output)
__device__ float g_wsplit[2 * (size_t)N3Q * DQ]; // 14 MB  (w_row hi/lo)

// ================= helpers ==================
__device__ __forceinline__ float tf32r(float x) {
    uint32_t u;
    asm("cvt.rna.tf32.f32 %0, %1;" : "=r"(u) : "f"(x));
    return __uint_as_float(u);
}

__device__ __forceinline__ void mma_tf32_16x8x8(float* c, const uint32_t* a, const uint32_t* b) {
    asm volatile(
        "mma.sync.aligned.m16n8k8.row.col.f32.tf32.tf32.f32 "
        "{%0,%1,%2,%3}, {%4,%5,%6,%7}, {%8,%9}, {%0,%1,%2,%3};"
        : "+f"(c[0]), "+f"(c[1]), "+f"(c[2]), "+f"(c[3])
        : "r"(a[0]), "r"(a[1]), "r"(a[2]), "r"(a[3]), "r"(b[0]), "r"(b[1]));
}

__device__ __forceinline__ uint32_t smem_u32(const void* p) {
    uint32_t a;
    asm("{ .reg .u64 t; cvta.to.shared.u64 t, %1; cvt.u32.u64 %0, t; }"
        : "=r"(a) : "l"(p));
    return a;
}

__device__ __forceinline__ void cpasync16(uint32_t dst, const void* src) {
    asm volatile("cp.async.cg.shared.global [%0], [%1], 16;" :: "r"(dst), "l"(src));
}
__device__ __forceinline__ void cp_commit() {
    asm volatile("cp.async.commit_group;" ::: "memory");
}
__device__ __forceinline__ void cp_wait1() {
    asm volatile("cp.async.wait_group 1;" ::: "memory");
}

// =================================================================
// Kernel 0: elementwise tf32 hi/lo split (precompute for mma GEMM)
// =================================================================
__global__ __launch_bounds__(256) void split_hi_lo(
    const float* __restrict__ in, float* __restrict__ hi,
    float* __restrict__ lo, int n4)
{
    int i = blockIdx.x * 256 + threadIdx.x;
    if (i >= n4) return;
    float4 v = ((const float4*)in)[i];
    float4 h, w;
    h.x = tf32r(v.x); w.x = tf32r(v.x - h.x);
    h.y = tf32r(v.y); w.y = tf32r(v.y - h.y);
    h.z = tf32r(v.z); w.z = tf32r(v.z - h.z);
    h.w = tf32r(v.w); w.w = tf32r(v.w - h.w);
    ((float4*)hi)[i] = h;
    ((float4*)lo)[i] = w;
}

// =================================================================
// Kernel 1a: mma_v2 GEMM: C = A*B^T + bias via tf32 x3 (pre-split).
// Tile 128x128, K-chunk 16, cp.async 2-stage, 8 warps, 2 CTAs/SM.
// smem/stage: Ah|Al|Bh|Bl each 128x20 words (padded, conflict-free).
// =================================================================
#define MV2_STAGE_B  40960       // 4 arrays * 2560 words * 4B
#define MV2_ARR_B    10240
#define MV2_SMEM     (2 * MV2_STAGE_B)

__global__ __launch_bounds__(256, 2) void qkv_gemm_mma2(
    const float* __restrict__ Ahi, const float* __restrict__ Alo,
    const float* __restrict__ Bhi, const float* __restrict__ Blo,
    const float* __restrict__ bias, float* __restrict__ C)
{
    extern __shared__ uint32_t sm2[];
    const int tid = threadIdx.x;
    const int m0 = blockIdx.y * 128;
    const int n0 = blockIdx.x * 128;
    const int w  = tid >> 5;
    const int l  = tid & 31;
    const int g  = l >> 2;
    const int q  = l & 3;
    const int wm = (w & 3) * 32;
    const int wn = (w >> 2) * 64;

    // staging map: 256 threads cover 128 rows x 2 half-rows of 8 words each
    const int srow = tid >> 1;
    const int scol = (tid & 1) * 8;           // word col 0 or 8
    const uint32_t smb = smem_u32(sm2);
    const uint32_t rowoff = (uint32_t)(srow * 20 + scol) * 4;

    const float* pAhi = Ahi + (size_t)(m0 + srow) * DQ + scol;
    const float* pAlo = Alo + (size_t)(m0 + srow) * DQ + scol;
    const float* pBhi = Bhi + (size_t)(n0 + srow) * DQ + scol;
    const float* pBlo = Blo + (size_t)(n0 + srow) * DQ + scol;

#define MV2_ISSUE(ch2) do {                                                   \
    const uint32_t d = smb + ((ch2) & 1) * MV2_STAGE_B + rowoff;              \
    const float* sA0 = pAhi + (ch2) * 16;                                     \
    const float* sA1 = pAlo + (ch2) * 16;                                     \
    const float* sB0 = pBhi + (ch2) * 16;                                     \
    const float* sB1 = pBlo + (ch2) * 16;                                     \
    cpasync16(d,                    sA0); cpasync16(d + 16,                    sA0 + 4); \
    cpasync16(d + MV2_ARR_B,        sA1); cpasync16(d + MV2_ARR_B + 16,        sA1 + 4); \
    cpasync16(d + 2 * MV2_ARR_B,    sB0); cpasync16(d + 2 * MV2_ARR_B + 16,    sB0 + 4); \
    cpasync16(d + 3 * MV2_ARR_B,    sB1); cpasync16(d + 3 * MV2_ARR_B + 16,    sB1 + 4); \
} while (0)

    float c[2][8][4];
#pragma unroll
    for (int mi = 0; mi < 2; mi++)
#pragma unroll
        for (int ni = 0; ni < 8; ni++)
#pragma unroll
            for (int t = 0; t < 4; t++) c[mi][ni][t] = 0.f;

    MV2_ISSUE(0); cp_commit();
    MV2_ISSUE(1); cp_commit();

    const int NCH = DQ / 16;   // 48
    for (int ch = 0; ch < NCH; ch++) {
        cp_wait1();
        __syncthreads();

        const uint32_t* Sw  = sm2 + (ch & 1) * (MV2_STAGE_B / 4);
        const uint32_t* A_h = Sw;
        const uint32_t* A_l = Sw + 2560;
        const uint32_t* B_h = Sw + 5120;
        const uint32_t* B_l = Sw + 7680;

#pragma unroll
        for (int k0 = 0; k0 < 16; k0 += 8) {
            uint32_t ah[2][4], al[2][4], bh[8][2], bl[8][2];
#pragma unroll
            for (int mi = 0; mi < 2; mi++) {
                const int r = wm + mi * 16 + g;
                ah[mi][0] = A_h[r * 20 + k0 + q];
                ah[mi][1] = A_h[(r + 8) * 20 + k0 + q];
                ah[mi][2] = A_h[r * 20 + k0 + q + 4];
                ah[mi][3] = A_h[(r + 8) * 20 + k0 + q + 4];
                al[mi][0] = A_l[r * 20 + k0 + q];
                al[mi][1] = A_l[(r + 8) * 20 + k0 + q];
                al[mi][2] = A_l[r * 20 + k0 + q + 4];
                al[mi][3] = A_l[(r + 8) * 20 + k0 + q + 4];
            }
#pragma unroll
            for (int ni = 0; ni < 8; ni++) {
                const int rn = wn + ni * 8 + g;
                bh[ni][0] = B_h[rn * 20 + k0 + q];
                bh[ni][1] = B_h[rn * 20 + k0 + q + 4];
                bl[ni][0] = B_l[rn * 20 + k0 + q];
                bl[ni][1] = B_l[rn * 20 + k0 + q + 4];
            }
            // product-major ordering: 16 independent accumulators per product
#pragma unroll
            for (int mi = 0; mi < 2; mi++)
#pragma unroll
                for (int ni = 0; ni < 8; ni++)
                    mma_tf32_16x8x8(c[mi][ni], ah[mi], bh[ni]);
#pragma unroll
            for (int mi = 0; mi < 2; mi++)
#pragma unroll
                for (int ni = 0; ni < 8; ni++)
                    mma_tf32_16x8x8(c[mi][ni], ah[mi], bl[ni]);
#pragma unroll
            for (int mi = 0; mi < 2; mi++)
#pragma unroll
                for (int ni = 0; ni < 8; ni++)
                    mma_tf32_16x8x8(c[mi][ni], al[mi], bh[ni]);
        }
        __syncthreads();
        if (ch + 2 < NCH) MV2_ISSUE(ch + 2);
        cp_commit();
    }

    // ---- epilogue: bias + store ----
#pragma unroll
    for (int ni = 0; ni < 8; ni++) {
        const int col = n0 + wn + ni * 8 + 2 * q;
        const float2 bv = *(const float2*)(bias + col);
#pragma unroll
        for (int mi = 0; mi < 2; mi++) {
            const int row0 = m0 + wm + mi * 16 + g;
            float2 o0 = make_float2(c[mi][ni][0] + bv.x, c[mi][ni][1] + bv.y);
            float2 o1 = make_float2(c[mi][ni][2] + bv.x, c[mi][ni][3] + bv.y);
            *(float2*)(C + (size_t)row0 * N3Q + col)       = o0;
            *(float2*)(C + (size_t)(row0 + 8) * N3Q + col) = o1;
        }
    }
#undef MV2_ISSUE
}

// =================================================================
// Kernel 1b: FFMA SGEMM (R2, proven): C = A*B^T + bias
// =================================================================
__global__ __launch_bounds__(256) void sgemm_nt_bias(
    const float* __restrict__ A, const float* __restrict__ B,
    const float* __restrict__ bias, float* __restrict__ C,
    int M, int N, int K)
{
    __shared__ float As[16][132];
    __shared__ float Bs[16][132];
    const int tid = threadIdx.x;
    const int bm = blockIdx.y * 128;
    const int bn = blockIdx.x * 128;
    const int lr = tid >> 2;
    const int lc = (tid & 3) << 2;
    const int tx = tid & 15;
    const int ty = tid >> 4;

    const float* Ap = A + (size_t)(bm + lr) * K + lc;
    const float* Bp = B + (size_t)(bn + lr) * K + lc;

    float4 pa0 = *(const float4*)Ap;
    float4 pa1 = *(const float4*)(Ap + (size_t)64 * K);
    float4 pb0 = *(const float4*)Bp;
    float4 pb1 = *(const float4*)(Bp + (size_t)64 * K);

    float acc[8][8];
#pragma unroll
    for (int i = 0; i < 8; i++)
#pragma unroll
        for (int j = 0; j < 8; j++) acc[i][j] = 0.f;

    const int nk = K >> 4;
    for (int kt = 0; kt < nk; kt++) {
        As[lc + 0][lr]      = pa0.x; As[lc + 1][lr]      = pa0.y;
        As[lc + 2][lr]      = pa0.z; As[lc + 3][lr]      = pa0.w;
        As[lc + 0][lr + 64] = pa1.x; As[lc + 1][lr + 64] = pa1.y;
        As[lc + 2][lr + 64] = pa1.z; As[lc + 3][lr + 64] = pa1.w;
        Bs[lc + 0][lr]      = pb0.x; Bs[lc + 1][lr]      = pb0.y;
        Bs[lc + 2][lr]      = pb0.z; Bs[lc + 3][lr]      = pb0.w;
        Bs[lc + 0][lr + 64] = pb1.x; Bs[lc + 1][lr + 64] = pb1.y;
        Bs[lc + 2][lr + 64] = pb1.z; Bs[lc + 3][lr + 64] = pb1.w;
        __syncthreads();

        if (kt + 1 < nk) {
            Ap += 16; Bp += 16;
            pa0 = *(const float4*)Ap;
            pa1 = *(const float4*)(Ap + (size_t)64 * K);
            pb0 = *(const float4*)Bp;
            pb1 = *(const float4*)(Bp + (size_t)64 * K);
        }

#pragma unroll
        for (int k = 0; k < 16; k++) {
            float a[8], b[8];
            *(float4*)(a)     = *(const float4*)(&As[k][ty * 4]);
            *(float4*)(a + 4) = *(const float4*)(&As[k][ty * 4 + 64]);
            *(float4*)(b)     = *(const float4*)(&Bs[k][tx * 4]);
            *(float4*)(b + 4) = *(const float4*)(&Bs[k][tx * 4 + 64]);
#pragma unroll
            for (int i = 0; i < 8; i++)
#pragma unroll
                for (int j = 0; j < 8; j++)
                    acc[i][j] += a[i] * b[j];
        }
        __syncthreads();
    }

    float bv[8];
    *(float4*)(bv)     = *(const float4*)(bias + bn + tx * 4);
    *(float4*)(bv + 4) = *(const float4*)(bias + bn + tx * 4 + 64);
#pragma unroll
    for (int i = 0; i < 8; i++) {
        int m = bm + ((i < 4) ? (ty * 4 + i) : (ty * 4 + 60 + i));
        float4 o0 = make_float4(acc[i][0] + bv[0], acc[i][1] + bv[1],
                                acc[i][2] + bv[2], acc[i][3] + bv[3]);
        float4 o1 = make_float4(acc[i][4] + bv[4], acc[i][5] + bv[5],
                                acc[i][6] + bv[6], acc[i][7] + bv[7]);
        float* cp = C + (size_t)m * N + bn + tx * 4;
        *(float4*)cp        = o0;
        *(float4*)(cp + 64) = o1;
    }
}

// =================================================================
// Kernel 2: row logits   attn[h,i,j] = sum_{s,c} Q[s,i,h,c] K[s,j,h,c]
// =================================================================
__global__ __launch_bounds__(256) void row_logits(
    const float* __restrict__ qkv, float* __restrict__ attn)
{
    __shared__ float Qs[64][65];
    __shared__ float Ks[64][65];
    const int h  = blockIdx.z;
    const int i0 = blockIdx.y * 64;
    const int j0 = blockIdx.x * 64;
    const int tid  = threadIdx.x;
    const int lrow = tid >> 2;
    const int lcol = (tid & 3) << 4;
    const int tx = tid & 15;
    const int ty = tid >> 4;
    const int hb = h * DHQ;

    float acc[4][4];
#pragma unroll
    for (int i = 0; i < 4; i++)
#pragma unroll
        for (int j = 0; j < 4; j++) acc[i][j] = 0.f;

    for (int s = 0; s < SQ; s++) {
        const float* qrow = qkv + (size_t)(s * LQ + i0 + lrow) * N3Q + hb + lcol;
        const float* krow = qkv + (size_t)(s * LQ + j0 + lrow) * N3Q + DQ + hb + lcol;
#pragma unroll
        for (int u = 0; u < 16; u += 4) {
            float4 qa = *(const float4*)(qrow + u);
            Qs[lrow][lcol + u + 0] = qa.x; Qs[lrow][lcol + u + 1] = qa.y;
            Qs[lrow][lcol + u + 2] = qa.z; Qs[lrow][lcol + u + 3] = qa.w;
            float4 ka = *(const float4*)(krow + u);
            Ks[lrow][lcol + u + 0] = ka.x; Ks[lrow][lcol + u + 1] = ka.y;
            Ks[lrow][lcol + u + 2] = ka.z; Ks[lrow][lcol + u + 3] = ka.w;
        }
        __syncthreads();
#pragma unroll 16
        for (int cix = 0; cix < DHQ; cix++) {
            float a[4], b[4];
#pragma unroll
            for (int r = 0; r < 4; r++) a[r] = Qs[ty * 4 + r][cix];
#pragma unroll
            for (int r = 0; r < 4; r++) b[r] = Ks[tx * 4 + r][cix];
#pragma unroll
            for (int i = 0; i < 4; i++)
#pragma unroll
                for (int j = 0; j < 4; j++)
                    acc[i][j] += a[i] * b[j];
        }
        __syncthreads();
    }
#pragma unroll
    for (int i = 0; i < 4; i++) {
        float4 v = make_float4(acc[i][0], acc[i][1], acc[i][2], acc[i][3]);
        *(float4*)&attn[(size_t)h * LQ * LQ + (i0 + ty * 4 + i) * LQ + j0 + tx * 4] = v;
    }
}

// =================================================================
// Kernel 3: softmax over last dim (256) of attn[h,i,:]
// =================================================================
__global__ __launch_bounds__(256) void softmax_row(float* __restrict__ attn)
{
    const int row = blockIdx.x;
    float* p = attn + (size_t)row * LQ;
    const int t = threadIdx.x;
    float v = p[t];

    __shared__ float red[8];
    float m = v;
#pragma unroll
    for (int o = 16; o > 0; o >>= 1) m = fmaxf(m, __shfl_xor_sync(0xffffffffu, m, o));
    if ((t & 31) == 0) red[t >> 5] = m;
    __syncthreads();
    float mm = red[0];
#pragma unroll
    for (int k = 1; k < 8; k++) mm = fmaxf(mm, red[k]);
    __syncthreads();

    float e = expf(v - mm);
    float s = e;
#pragma unroll
    for (int o = 16; o > 0; o >>= 1) s += __shfl_xor_sync(0xffffffffu, s, o);
    if ((t & 31) == 0) red[t >> 5] = s;
    __syncthreads();
    float tot = 0.f;
#pragma unroll
    for (int k = 0; k < 8; k++) tot += red[k];

    p[t] = e / tot;
}

// =================================================================
// Kernel 4: row AV  out[s,i,h,d] = sum_j attn[h,i,j] V[s,j,h,d]
// =================================================================
__global__ __launch_bounds__(256) void row_av(
    const float* __restrict__ attn, const float* __restrict__ qkv,
    float* __restrict__ out)
{
    __shared__ float As[64][36];
    __shared__ float Vs[32][68];
    const int i0 = blockIdx.x * 64;
    const int h  = blockIdx.y;
    const int s  = blockIdx.z;
    const int tid = threadIdx.x;
    const int tx = tid & 15, ty = tid >> 4;
    const int a_row = tid >> 2, a_col = (tid & 3) << 3;
    const int v_row = tid >> 3, v_col = (tid & 7) << 3;

    float acc[4][4];
#pragma unroll
    for (int i = 0; i < 4; i++)
#pragma unroll
        for (int j = 0; j < 4; j++) acc[i][j] = 0.f;

    for (int jb = 0; jb < LQ; jb += 32) {
        const float* ap = attn + (size_t)h * LQ * LQ + (i0 + a_row) * LQ + jb + a_col;
        *(float4*)&As[a_row][a_col]     = *(const float4*)ap;
        *(float4*)&As[a_row][a_col + 4] = *(const float4*)(ap + 4);
        const float* vp = qkv + (size_t)(s * LQ + jb + v_row) * N3Q + 2 * DQ + h * DHQ + v_col;
        *(float4*)&Vs[v_row][v_col]     = *(const float4*)vp;
        *(float4*)&Vs[v_row][v_col + 4] = *(const float4*)(vp + 4);
        __syncthreads();
#pragma unroll 16
        for (int j = 0; j < 32; j++) {
            float a[4], v[4];
#pragma unroll
            for (int r = 0; r < 4; r++) a[r] = As[ty * 4 + r][j];
#pragma unroll
            for (int r = 0; r < 4; r++) v[r] = Vs[j][tx * 4 + r];
#pragma unroll
            for (int i = 0; i < 4; i++)
#pragma unroll
                for (int d = 0; d < 4; d++)
                    acc[i][d] += a[i] * v[d];
        }
        __syncthreads();
    }
#pragma unroll
    for (int i = 0; i < 4; i++) {
        float4 v = make_float4(acc[i][0], acc[i][1], acc[i][2], acc[i][3]);
        *(float4*)&out[(size_t)(s * LQ + i0 + ty * 4 + i) * DQ + h * DHQ + tx * 4] = v;
    }
}

// =================================================================
// Kernel 5: out[row,:] = LN(X[row,:] + R[row,:]) * g + b   (D=768)
// =================================================================
__global__ __launch_bounds__(256) void add_ln(
    const float* __restrict__ X, const float* __restrict__ R,
    const float* __restrict__ g, const float* __restrict__ b,
    float* __restrict__ out)
{
    const int row = blockIdx.x;
    const int t = threadIdx.x;
    const float* x = X + (size_t)row * DQ;
    const float* r = R + (size_t)row * DQ;
    float y0 = x[t]       + r[t];
    float y1 = x[t + 256] + r[t + 256];
    float y2 = x[t + 512] + r[t + 512];
    float s = y0 + y1 + y2;
    float qv = y0 * y0 + y1 * y1 + y2 * y2;

    __shared__ float ss[8], qq[8];
#pragma unroll
    for (int o = 16; o > 0; o >>= 1) {
        s  += __shfl_xor_sync(0xffffffffu, s, o);
        qv += __shfl_xor_sync(0xffffffffu, qv, o);
    }
    if ((t & 31) == 0) { ss[t >> 5] = s; qq[t >> 5] = qv; }
    __syncthreads();
    if (t < 32) {
        float s2 = (t < 8) ? ss[t] : 0.f;
        float q2 = (t < 8) ? qq[t] : 0.f;
#pragma unroll
        for (int o = 4; o > 0; o >>= 1) {
            s2 += __shfl_xor_sync(0xffffffffu, s2, o);
            q2 += __shfl_xor_sync(0xffffffffu, q2, o);
        }
        if (t == 0) { ss[0] = s2; qq[0] = q2; }
    }
    __syncthreads();
    const float invD = 1.f / (float)DQ;
    float mean = ss[0] * invD;
    float var  = qq[0] * invD - mean * mean;
    float inv  = rsqrtf(var + 1e-5f);
    float* o = out + (size_t)row * DQ;
    o[t]       = (y0 - mean) * inv * g[t]       + b[t];
    o[t + 256] = (y1 - mean) * inv * g[t + 256] + b[t + 256];
    o[t + 512] = (y2 - mean) * inv * g[t + 512] + b[t + 512];
}

// =================================================================
// Kernel 7: column attention. One CTA per (l,h); 128 threads.
// =================================================================
__global__ __launch_bounds__(128) void col_attn_kernel(
    const float* __restrict__ qkv, float* __restrict__ out)
{
    extern __shared__ float sm[];
    float* P  = sm;                 // [128*128] transposed: P[j*128 + i]
    float* Kt = sm + 128 * 128;     // [64*128]
    float* Vt = Kt + 64 * 128;      // [64*128]

    const int l = blockIdx.x;
    const int h = blockIdx.y;
    const int t = threadIdx.x;
    const int base = l * N3Q + h * DHQ;

    const float* krow = qkv + (size_t)(t * LQ) * N3Q + base + DQ;
    const float* vrow = krow + DQ;
#pragma unroll
    for (int c = 0; c < DHQ; c += 4) {
        float4 kv = *(const float4*)(krow + c);
        Kt[(c + 0) * 128 + t] = kv.x; Kt[(c + 1) * 128 + t] = kv.y;
        Kt[(c + 2) * 128 + t] = kv.z; Kt[(c + 3) * 128 + t] = kv.w;
        float4 vv = *(const float4*)(vrow + c);
        Vt[(c + 0) * 128 + t] = vv.x; Vt[(c + 1) * 128 + t] = vv.y;
        Vt[(c + 2) * 128 + t] = vv.z; Vt[(c + 3) * 128 + t] = vv.w;
    }
    float q[DHQ];
    const float* qrow = qkv + (size_t)(t * LQ) * N3Q + base;
#pragma unroll
    for (int c = 0; c < DHQ; c += 4) {
        float4 qv = *(const float4*)(qrow + c);
        q[c] = qv.x; q[c + 1] = qv.y; q[c + 2] = qv.z; q[c + 3] = qv.w;
    }
    __syncthreads();

    for (int j = 0; j < SQ; j++) {
        float a0 = 0.f, a1 = 0.f, a2 = 0.f, a3 = 0.f;
#pragma unroll
        for (int c = 0; c < DHQ; c += 4) {
            a0 += q[c]     * Kt[(c)     * 128 + j];
            a1 += q[c + 1] * Kt[(c + 1) * 128 + j];
            a2 += q[c + 2] * Kt[(c + 2) * 128 + j];
            a3 += q[c + 3] * Kt[(c + 3) * 128 + j];
        }
        P[j * 128 + t] = (a0 + a1) + (a2 + a3);
    }

    float m = -3.4e38f;
    for (int j = 0; j < SQ; j++) m = fmaxf(m, P[j * 128 + t]);
    float ssum = 0.f;
    for (int j = 0; j < SQ; j++) {
        float e = expf(P[j * 128 + t] - m);
        P[j * 128 + t] = e;
        ssum += e;
    }
    const float inv = 1.f / ssum;

    float o[DHQ];
#pragma unroll
    for (int d = 0; d < DHQ; d++) o[d] = 0.f;
    for (int j = 0; j < SQ; j++) {
        float p = P[j * 128 + t];
#pragma unroll
        for (int d = 0; d < DHQ; d++) o[d] += p * Vt[d * 128 + j];
    }

    float* orow = out + (size_t)(t * LQ + l) * DQ + h * DHQ;
#pragma unroll
    for (int d = 0; d < DHQ; d += 4) {
        float4 v = make_float4(o[d] * inv, o[d + 1] * inv, o[d + 2] * inv, o[d + 3] * inv);
        *(float4*)(orow + d) = v;
    }
}

// =================================================================
extern "C" void kernel_launch(void* const* d_in, const int* in_sizes, int n_in,
                              void* d_out, int out_size)
{
    const float* x     = (const float*)d_in[0];
    const float* w_row = (const float*)d_in[1];
    const float* b_row = (const float*)d_in[2];
    const float* w_col = (const float*)d_in[3];
    const float* b_col = (const float*)d_in[4];
    const float* g1    = (const float*)d_in[5];
    const float* beta1 = (const float*)d_in[6];
    const float* g2    = (const float*)d_in[7];
    const float* beta2 = (const float*)d_in[8];
    float* out = (float*)d_out;

    float *qkv, *attn, *tmp, *out1, *wsp;
    cudaGetSymbolAddress((void**)&qkv,  g_qkv);
    cudaGetSymbolAddress((void**)&attn, g_attn);
    cudaGetSymbolAddress((void**)&tmp,  g_tmp);
    cudaGetSymbolAddress((void**)&out1, g_out1);
    cudaGetSymbolAddress((void**)&wsp,  g_wsplit);

    cudaFuncSetAttribute(col_attn_kernel,
                         cudaFuncAttributeMaxDynamicSharedMemorySize, 131072);
    cudaFuncSetAttribute(qkv_gemm_mma2,
                         cudaFuncAttributeMaxDynamicSharedMemorySize, MV2_SMEM);

    // --- row stage: pre-split + mma_v2 GEMM ---
    const int n4A = MQ * DQ / 4;     // 6291456
    const int n4B = N3Q * DQ / 4;    // 442368
    split_hi_lo<<<n4A / 256, 256>>>(x, tmp, out1, n4A);
    split_hi_lo<<<n4B / 256, 256>>>(w_row, wsp, wsp + (size_t)N3Q * DQ, n4B);
    qkv_gemm_mma2<<<dim3(N3Q / 128, MQ / 128), 256, MV2_SMEM>>>(
        tmp, out1, wsp, wsp + (size_t)N3Q * DQ, b_row, qkv);

    row_logits<<<dim3(4, 4, HQ), 256>>>(qkv, attn);
    softmax_row<<<HQ * LQ, 256>>>(attn);
    row_av<<<dim3(4, HQ, SQ), 256>>>(attn, qkv, tmp);
    add_ln<<<MQ, 256>>>(x, tmp, g1, beta1, out1);

    // --- column stage: FFMA GEMM anchor ---
    sgemm_nt_bias<<<dim3(N3Q / 128, MQ / 128), 256>>>(out1, w_col, b_col, qkv, MQ, N3Q, DQ);
    col_attn_kernel<<<dim3(LQ, HQ), 128, 131072>>>(qkv, tmp);
    add_ln<<<MQ, 256>>>(out1, tmp, g2, beta2, out);
}

// round 11
// speedup vs baseline: 1.7128x; 1.5121x over previous
#include <cuda_runtime.h>
#include <cuda_bf16.h>
#include <math.h>
#include <stdint.h>

// Shapes: B=1, S=128, L=256, D=768 (H=12, dh=64), M = S*L = 32768, 3D = 2304.
#define SQ   128
#define LQ   256
#define DQ   768
#define HQ   12
#define DHQ  64
#define MQ   (SQ * LQ)      // 32768
#define N3Q  (3 * DQ)       // 2304
#define NSP  8              // s-splits for row_logits

// ---------------- scratch (no cudaMalloc allowed) ----------------
__device__ float g_qkv[(size_t)MQ * N3Q];        // 302 MB
__device__ float g_attn[HQ * LQ * LQ];           // 3 MB
__device__ float g_tmp[(size_t)MQ * DQ];         // 100 MB: bf16 A hi/lo splits, then attn outputs
__device__ float g_out1[(size_t)MQ * DQ];        // 100 MB: row-logit partials, then LN1 output
__device__ float g_wsplit[2 * (size_t)N3Q * DQ]; // 14 MB : bf16 W hi/lo splits

// ================= helpers ==================
__device__ __forceinline__ void mma_bf16_16x8x16(float* c, const uint32_t* a, const uint32_t* b) {
    asm volatile(
        "mma.sync.aligned.m16n8k16.row.col.f32.bf16.bf16.f32 "
        "{%0,%1,%2,%3}, {%4,%5,%6,%7}, {%8,%9}, {%0,%1,%2,%3};"
        : "+f"(c[0]), "+f"(c[1]), "+f"(c[2]), "+f"(c[3])
        : "r"(a[0]), "r"(a[1]), "r"(a[2]), "r"(a[3]), "r"(b[0]), "r"(b[1]));
}

__device__ __forceinline__ uint32_t smem_u32(const void* p) {
    uint32_t a;
    asm("{ .reg .u64 t; cvta.to.shared.u64 t, %1; cvt.u32.u64 %0, t; }"
        : "=r"(a) : "l"(p));
    return a;
}

__device__ __forceinline__ void cpasync16(uint32_t dst, const void* src) {
    asm volatile("cp.async.cg.shared.global [%0], [%1], 16;" :: "r"(dst), "l"(src));
}
__device__ __forceinline__ void cp_commit() {
    asm volatile("cp.async.commit_group;" ::: "memory");
}
__device__ __forceinline__ void cp_wait1() {
    asm volatile("cp.async.wait_group 1;" ::: "memory");
}

// =================================================================
// Kernel 0: elementwise bf16 hi/lo split (precompute for mma GEMM)
// hi = bf16(x); lo = bf16(x - hi)   (x - hi exact in fp32)
// =================================================================
__global__ __launch_bounds__(256) void split_bf16(
    const float* __restrict__ in, __nv_bfloat16* __restrict__ hi,
    __nv_bfloat16* __restrict__ lo, int n4)
{
    int i = blockIdx.x * 256 + threadIdx.x;
    if (i >= n4) return;
    float4 v = ((const float4*)in)[i];
    __nv_bfloat16 h0 = __float2bfloat16_rn(v.x);
    __nv_bfloat16 h1 = __float2bfloat16_rn(v.y);
    __nv_bfloat16 h2 = __float2bfloat16_rn(v.z);
    __nv_bfloat16 h3 = __float2bfloat16_rn(v.w);
    __nv_bfloat16 l0 = __float2bfloat16_rn(v.x - __bfloat162float(h0));
    __nv_bfloat16 l1 = __float2bfloat16_rn(v.y - __bfloat162float(h1));
    __nv_bfloat16 l2 = __float2bfloat16_rn(v.z - __bfloat162float(h2));
    __nv_bfloat16 l3 = __float2bfloat16_rn(v.w - __bfloat162float(h3));
    uint32_t ph0 = ((uint32_t)__bfloat16_as_ushort(h1) << 16) | __bfloat16_as_ushort(h0);
    uint32_t ph1 = ((uint32_t)__bfloat16_as_ushort(h3) << 16) | __bfloat16_as_ushort(h2);
    uint32_t pl0 = ((uint32_t)__bfloat16_as_ushort(l1) << 16) | __bfloat16_as_ushort(l0);
    uint32_t pl1 = ((uint32_t)__bfloat16_as_ushort(l3) << 16) | __bfloat16_as_ushort(l2);
    ((uint2*)hi)[i] = make_uint2(ph0, ph1);
    ((uint2*)lo)[i] = make_uint2(pl0, pl1);
}

// =================================================================
// Kernel 1: bf16 x3-split GEMM: C[M,2304] = A*B^T + bias
// Tile 128x128, K-chunk 32 (2 x k16 mma steps), cp.async 2-stage,
// 8 warps (4m x 2n), 2 CTAs/SM. smem rows padded to 20 words.
// =================================================================
#define MV2_STAGE_B  40960
#define MV2_ARR_B    10240
#define MV2_SMEM     (2 * MV2_STAGE_B)

__global__ __launch_bounds__(256, 2) void qkv_gemm_bf16(
    const __nv_bfloat16* __restrict__ Ahi, const __nv_bfloat16* __restrict__ Alo,
    const __nv_bfloat16* __restrict__ Bhi, const __nv_bfloat16* __restrict__ Blo,
    const float* __restrict__ bias, float* __restrict__ C)
{
    extern __shared__ uint32_t sm2[];
    const int tid = threadIdx.x;
    const int m0 = blockIdx.y * 128;
    const int n0 = blockIdx.x * 128;
    const int w  = tid >> 5;
    const int l  = tid & 31;
    const int g  = l >> 2;
    const int q  = l & 3;
    const int wm = (w & 3) * 32;
    const int wn = (w >> 2) * 64;

    // staging: 2 threads per row; each covers 16 bf16 = 32B = 2 x cp.async16
    const int srow  = tid >> 1;
    const int shalf = tid & 1;
    const uint32_t smb = smem_u32(sm2);
    const uint32_t rowoff = (uint32_t)(srow * 20 + shalf * 8) * 4;

    const __nv_bfloat16* pAhi = Ahi + (size_t)(m0 + srow) * DQ + shalf * 16;
    const __nv_bfloat16* pAlo = Alo + (size_t)(m0 + srow) * DQ + shalf * 16;
    const __nv_bfloat16* pBhi = Bhi + (size_t)(n0 + srow) * DQ + shalf * 16;
    const __nv_bfloat16* pBlo = Blo + (size_t)(n0 + srow) * DQ + shalf * 16;

#define BF_ISSUE(ch2) do {                                                    \
    const uint32_t d = smb + ((ch2) & 1) * MV2_STAGE_B + rowoff;              \
    const __nv_bfloat16* sA0 = pAhi + (ch2) * 32;                             \
    const __nv_bfloat16* sA1 = pAlo + (ch2) * 32;                             \
    const __nv_bfloat16* sB0 = pBhi + (ch2) * 32;                             \
    const __nv_bfloat16* sB1 = pBlo + (ch2) * 32;                             \
    cpasync16(d,                 sA0); cpasync16(d + 16,                 sA0 + 8); \
    cpasync16(d + MV2_ARR_B,     sA1); cpasync16(d + MV2_ARR_B + 16,     sA1 + 8); \
    cpasync16(d + 2 * MV2_ARR_B, sB0); cpasync16(d + 2 * MV2_ARR_B + 16, sB0 + 8); \
    cpasync16(d + 3 * MV2_ARR_B, sB1); cpasync16(d + 3 * MV2_ARR_B + 16, sB1 + 8); \
} while (0)

    float c[2][8][4];
#pragma unroll
    for (int mi = 0; mi < 2; mi++)
#pragma unroll
        for (int ni = 0; ni < 8; ni++)
#pragma unroll
            for (int t = 0; t < 4; t++) c[mi][ni][t] = 0.f;

    BF_ISSUE(0); cp_commit();
    BF_ISSUE(1); cp_commit();

    const int NCH = DQ / 32;   // 24
    for (int ch = 0; ch < NCH; ch++) {
        cp_wait1();
        __syncthreads();

        const uint32_t* Sw  = sm2 + (ch & 1) * (MV2_STAGE_B / 4);
        const uint32_t* A_h = Sw;
        const uint32_t* A_l = Sw + 2560;
        const uint32_t* B_h = Sw + 5120;
        const uint32_t* B_l = Sw + 7680;

#pragma unroll
        for (int ks = 0; ks < 2; ks++) {
            const int ws = ks * 8;
            uint32_t ah[2][4], al[2][4], bh[8][2], bl[8][2];
#pragma unroll
            for (int mi = 0; mi < 2; mi++) {
                const int r = wm + mi * 16 + g;
                ah[mi][0] = A_h[r * 20 + ws + q];
                ah[mi][1] = A_h[(r + 8) * 20 + ws + q];
                ah[mi][2] = A_h[r * 20 + ws + q + 4];
                ah[mi][3] = A_h[(r + 8) * 20 + ws + q + 4];
                al[mi][0] = A_l[r * 20 + ws + q];
                al[mi][1] = A_l[(r + 8) * 20 + ws + q];
                al[mi][2] = A_l[r * 20 + ws + q + 4];
                al[mi][3] = A_l[(r + 8) * 20 + ws + q + 4];
            }
#pragma unroll
            for (int ni = 0; ni < 8; ni++) {
                const int rn = wn + ni * 8 + g;
                bh[ni][0] = B_h[rn * 20 + ws + q];
                bh[ni][1] = B_h[rn * 20 + ws + q + 4];
                bl[ni][0] = B_l[rn * 20 + ws + q];
                bl[ni][1] = B_l[rn * 20 + ws + q + 4];
            }
#pragma unroll
            for (int mi = 0; mi < 2; mi++)
#pragma unroll
                for (int ni = 0; ni < 8; ni++)
                    mma_bf16_16x8x16(c[mi][ni], ah[mi], bh[ni]);
#pragma unroll
            for (int mi = 0; mi < 2; mi++)
#pragma unroll
                for (int ni = 0; ni < 8; ni++)
                    mma_bf16_16x8x16(c[mi][ni], ah[mi], bl[ni]);
#pragma unroll
            for (int mi = 0; mi < 2; mi++)
#pragma unroll
                for (int ni = 0; ni < 8; ni++)
                    mma_bf16_16x8x16(c[mi][ni], al[mi], bh[ni]);
        }
        __syncthreads();
        if (ch + 2 < NCH) BF_ISSUE(ch + 2);
        cp_commit();
    }

    // ---- epilogue: bias + store ----
#pragma unroll
    for (int ni = 0; ni < 8; ni++) {
        const int col = n0 + wn + ni * 8 + 2 * q;
        const float2 bv = *(const float2*)(bias + col);
#pragma unroll
        for (int mi = 0; mi < 2; mi++) {
            const int row0 = m0 + wm + mi * 16 + g;
            float2 o0 = make_float2(c[mi][ni][0] + bv.x, c[mi][ni][1] + bv.y);
            float2 o1 = make_float2(c[mi][ni][2] + bv.x, c[mi][ni][3] + bv.y);
            *(float2*)(C + (size_t)row0 * N3Q + col)       = o0;
            *(float2*)(C + (size_t)(row0 + 8) * N3Q + col) = o1;
        }
    }
#undef BF_ISSUE
}

// =================================================================
// Kernel 2: row logits partials over s-chunks of 16:
// part[sp,h,i,j] = sum_{s in chunk sp} sum_c Q[s,i,h,c] K[s,j,h,c]
// =================================================================
__global__ __launch_bounds__(256) void row_logits_part(
    const float* __restrict__ qkv, float* __restrict__ part)
{
    __shared__ float Qs[64][65];
    __shared__ float Ks[64][65];
    const int zz = blockIdx.z;
    const int h  = zz / NSP;
    const int sp = zz % NSP;
    const int i0 = blockIdx.y * 64;
    const int j0 = blockIdx.x * 64;
    const int tid  = threadIdx.x;
    const int lrow = tid >> 2;
    const int lcol = (tid & 3) << 4;
    const int tx = tid & 15;
    const int ty = tid >> 4;
    const int hb = h * DHQ;

    float acc[4][4];
#pragma unroll
    for (int i = 0; i < 4; i++)
#pragma unroll
        for (int j = 0; j < 4; j++) acc[i][j] = 0.f;

    const int s1 = sp * (SQ / NSP) + (SQ / NSP);
    for (int s = sp * (SQ / NSP); s < s1; s++) {
        const float* qrow = qkv + (size_t)(s * LQ + i0 + lrow) * N3Q + hb + lcol;
        const float* krow = qkv + (size_t)(s * LQ + j0 + lrow) * N3Q + DQ + hb + lcol;
#pragma unroll
        for (int u = 0; u < 16; u += 4) {
            float4 qa = *(const float4*)(qrow + u);
            Qs[lrow][lcol + u + 0] = qa.x; Qs[lrow][lcol + u + 1] = qa.y;
            Qs[lrow][lcol + u + 2] = qa.z; Qs[lrow][lcol + u + 3] = qa.w;
            float4 ka = *(const float4*)(krow + u);
            Ks[lrow][lcol + u + 0] = ka.x; Ks[lrow][lcol + u + 1] = ka.y;
            Ks[lrow][lcol + u + 2] = ka.z; Ks[lrow][lcol + u + 3] = ka.w;
        }
        __syncthreads();
#pragma unroll 16
        for (int cix = 0; cix < DHQ; cix++) {
            float a[4], b[4];
#pragma unroll
            for (int r = 0; r < 4; r++) a[r] = Qs[ty * 4 + r][cix];
#pragma unroll
            for (int r = 0; r < 4; r++) b[r] = Ks[tx * 4 + r][cix];
#pragma unroll
            for (int i = 0; i < 4; i++)
#pragma unroll
                for (int j = 0; j < 4; j++)
                    acc[i][j] += a[i] * b[j];
        }
        __syncthreads();
    }
    float* dst = part + ((size_t)(sp * HQ + h)) * LQ * LQ;
#pragma unroll
    for (int i = 0; i < 4; i++) {
        float4 v = make_float4(acc[i][0], acc[i][1], acc[i][2], acc[i][3]);
        *(float4*)&dst[(size_t)(i0 + ty * 4 + i) * LQ + j0 + tx * 4] = v;
    }
}

// =================================================================
// Kernel 3: reduce partials + softmax over last dim (256)
// =================================================================
__global__ __launch_bounds__(256) void softmax_row(
    const float* __restrict__ part, float* __restrict__ attn)
{
    const int row = blockIdx.x;          // h*256 + i
    const int h = row >> 8;
    const int i = row & 255;
    const int t = threadIdx.x;

    float v = 0.f;
#pragma unroll
    for (int sp = 0; sp < NSP; sp++)
        v += part[((size_t)(sp * HQ + h)) * LQ * LQ + (size_t)i * LQ + t];

    __shared__ float red[8];
    float m = v;
#pragma unroll
    for (int o = 16; o > 0; o >>= 1) m = fmaxf(m, __shfl_xor_sync(0xffffffffu, m, o));
    if ((t & 31) == 0) red[t >> 5] = m;
    __syncthreads();
    float mm = red[0];
#pragma unroll
    for (int k = 1; k < 8; k++) mm = fmaxf(mm, red[k]);
    __syncthreads();

    float e = expf(v - mm);
    float s = e;
#pragma unroll
    for (int o = 16; o > 0; o >>= 1) s += __shfl_xor_sync(0xffffffffu, s, o);
    if ((t & 31) == 0) red[t >> 5] = s;
    __syncthreads();
    float tot = 0.f;
#pragma unroll
    for (int k = 0; k < 8; k++) tot += red[k];

    attn[(size_t)row * LQ + t] = e / tot;
}

// =================================================================
// Kernel 4: row AV  out[s,i,h,d] = sum_j attn[h,i,j] V[s,j,h,d]
// =================================================================
__global__ __launch_bounds__(256) void row_av(
    const float* __restrict__ attn, const float* __restrict__ qkv,
    float* __restrict__ out)
{
    __shared__ float As[64][36];
    __shared__ float Vs[32][68];
    const int i0 = blockIdx.x * 64;
    const int h  = blockIdx.y;
    const int s  = blockIdx.z;
    const int tid = threadIdx.x;
    const int tx = tid & 15, ty = tid >> 4;
    const int a_row = tid >> 2, a_col = (tid & 3) << 3;
    const int v_row = tid >> 3, v_col = (tid & 7) << 3;

    float acc[4][4];
#pragma unroll
    for (int i = 0; i < 4; i++)
#pragma unroll
        for (int j = 0; j < 4; j++) acc[i][j] = 0.f;

    for (int jb = 0; jb < LQ; jb += 32) {
        const float* ap = attn + (size_t)h * LQ * LQ + (i0 + a_row) * LQ + jb + a_col;
        *(float4*)&As[a_row][a_col]     = *(const float4*)ap;
        *(float4*)&As[a_row][a_col + 4] = *(const float4*)(ap + 4);
        const float* vp = qkv + (size_t)(s * LQ + jb + v_row) * N3Q + 2 * DQ + h * DHQ + v_col;
        *(float4*)&Vs[v_row][v_col]     = *(const float4*)vp;
        *(float4*)&Vs[v_row][v_col + 4] = *(const float4*)(vp + 4);
        __syncthreads();
#pragma unroll 16
        for (int j = 0; j < 32; j++) {
            float a[4], v[4];
#pragma unroll
            for (int r = 0; r < 4; r++) a[r] = As[ty * 4 + r][j];
#pragma unroll
            for (int r = 0; r < 4; r++) v[r] = Vs[j][tx * 4 + r];
#pragma unroll
            for (int i = 0; i < 4; i++)
#pragma unroll
                for (int d = 0; d < 4; d++)
                    acc[i][d] += a[i] * v[d];
        }
        __syncthreads();
    }
#pragma unroll
    for (int i = 0; i < 4; i++) {
        float4 v = make_float4(acc[i][0], acc[i][1], acc[i][2], acc[i][3]);
        *(float4*)&out[(size_t)(s * LQ + i0 + ty * 4 + i) * DQ + h * DHQ + tx * 4] = v;
    }
}

// =================================================================
// Kernel 5: out[row,:] = LN(X[row,:] + R[row,:]) * g + b   (D=768)
// =================================================================
__global__ __launch_bounds__(256) void add_ln(
    const float* __restrict__ X, const float* __restrict__ R,
    const float* __restrict__ g, const float* __restrict__ b,
    float* __restrict__ out)
{
    const int row = blockIdx.x;
    const int t = threadIdx.x;
    const float* x = X + (size_t)row * DQ;
    const float* r = R + (size_t)row * DQ;
    float y0 = x[t]       + r[t];
    float y1 = x[t + 256] + r[t + 256];
    float y2 = x[t + 512] + r[t + 512];
    float s = y0 + y1 + y2;
    float qv = y0 * y0 + y1 * y1 + y2 * y2;

    __shared__ float ss[8], qq[8];
#pragma unroll
    for (int o = 16; o > 0; o >>= 1) {
        s  += __shfl_xor_sync(0xffffffffu, s, o);
        qv += __shfl_xor_sync(0xffffffffu, qv, o);
    }
    if ((t & 31) == 0) { ss[t >> 5] = s; qq[t >> 5] = qv; }
    __syncthreads();
    if (t < 32) {
        float s2 = (t < 8) ? ss[t] : 0.f;
        float q2 = (t < 8) ? qq[t] : 0.f;
#pragma unroll
        for (int o = 4; o > 0; o >>= 1) {
            s2 += __shfl_xor_sync(0xffffffffu, s2, o);
            q2 += __shfl_xor_sync(0xffffffffu, q2, o);
        }
        if (t == 0) { ss[0] = s2; qq[0] = q2; }
    }
    __syncthreads();
    const float invD = 1.f / (float)DQ;
    float mean = ss[0] * invD;
    float var  = qq[0] * invD - mean * mean;
    float inv  = rsqrtf(var + 1e-5f);
    float* o = out + (size_t)row * DQ;
    o[t]       = (y0 - mean) * inv * g[t]       + b[t];
    o[t + 256] = (y1 - mean) * inv * g[t + 256] + b[t + 256];
    o[t + 512] = (y2 - mean) * inv * g[t + 512] + b[t + 512];
}

// =================================================================
// Kernel 7: column attention. One CTA per (l,h); 128 threads.
// =================================================================
__global__ __launch_bounds__(128) void col_attn_kernel(
    const float* __restrict__ qkv, float* __restrict__ out)
{
    extern __shared__ float sm[];
    float* P  = sm;                 // [128*128] transposed: P[j*128 + i]
    float* Kt = sm + 128 * 128;     // [64*128]
    float* Vt = Kt + 64 * 128;      // [64*128]

    const int l = blockIdx.x;
    const int h = blockIdx.y;
    const int t = threadIdx.x;
    const int base = l * N3Q + h * DHQ;

    const float* krow = qkv + (size_t)(t * LQ) * N3Q + base + DQ;
    const float* vrow = krow + DQ;
#pragma unroll
    for (int c = 0; c < DHQ; c += 4) {
        float4 kv = *(const float4*)(krow + c);
        Kt[(c + 0) * 128 + t] = kv.x; Kt[(c + 1) * 128 + t] = kv.y;
        Kt[(c + 2) * 128 + t] = kv.z; Kt[(c + 3) * 128 + t] = kv.w;
        float4 vv = *(const float4*)(vrow + c);
        Vt[(c + 0) * 128 + t] = vv.x; Vt[(c + 1) * 128 + t] = vv.y;
        Vt[(c + 2) * 128 + t] = vv.z; Vt[(c + 3) * 128 + t] = vv.w;
    }
    float q[DHQ];
    const float* qrow = qkv + (size_t)(t * LQ) * N3Q + base;
#pragma unroll
    for (int c = 0; c < DHQ; c += 4) {
        float4 qv = *(const float4*)(qrow + c);
        q[c] = qv.x; q[c + 1] = qv.y; q[c + 2] = qv.z; q[c + 3] = qv.w;
    }
    __syncthreads();

    for (int j = 0; j < SQ; j++) {
        float a0 = 0.f, a1 = 0.f, a2 = 0.f, a3 = 0.f;
#pragma unroll
        for (int c = 0; c < DHQ; c += 4) {
            a0 += q[c]     * Kt[(c)     * 128 + j];
            a1 += q[c + 1] * Kt[(c + 1) * 128 + j];
            a2 += q[c + 2] * Kt[(c + 2) * 128 + j];
            a3 += q[c + 3] * Kt[(c + 3) * 128 + j];
        }
        P[j * 128 + t] = (a0 + a1) + (a2 + a3);
    }

    float m = -3.4e38f;
    for (int j = 0; j < SQ; j++) m = fmaxf(m, P[j * 128 + t]);
    float ssum = 0.f;
    for (int j = 0; j < SQ; j++) {
        float e = expf(P[j * 128 + t] - m);
        P[j * 128 + t] = e;
        ssum += e;
    }
    const float inv = 1.f / ssum;

    float o[DHQ];
#pragma unroll
    for (int d = 0; d < DHQ; d++) o[d] = 0.f;
    for (int j = 0; j < SQ; j++) {
        float p = P[j * 128 + t];
#pragma unroll
        for (int d = 0; d < DHQ; d++) o[d] += p * Vt[d * 128 + j];
    }

    float* orow = out + (size_t)(t * LQ + l) * DQ + h * DHQ;
#pragma unroll
    for (int d = 0; d < DHQ; d += 4) {
        float4 v = make_float4(o[d] * inv, o[d + 1] * inv, o[d + 2] * inv, o[d + 3] * inv);
        *(float4*)(orow + d) = v;
    }
}

// =================================================================
extern "C" void kernel_launch(void* const* d_in, const int* in_sizes, int n_in,
                              void* d_out, int out_size)
{
    const float* x     = (const float*)d_in[0];
    const float* w_row = (const float*)d_in[1];
    const float* b_row = (const float*)d_in[2];
    const float* w_col = (const float*)d_in[3];
    const float* b_col = (const float*)d_in[4];
    const float* g1    = (const float*)d_in[5];
    const float* beta1 = (const float*)d_in[6];
    const float* g2    = (const float*)d_in[7];
    const float* beta2 = (const float*)d_in[8];
    float* out = (float*)d_out;

    float *qkv, *attn, *tmp, *out1, *wsp;
    cudaGetSymbolAddress((void**)&qkv,  g_qkv);
    cudaGetSymbolAddress((void**)&attn, g_attn);
    cudaGetSymbolAddress((void**)&tmp,  g_tmp);
    cudaGetSymbolAddress((void**)&out1, g_out1);
    cudaGetSymbolAddress((void**)&wsp,  g_wsplit);

    __nv_bfloat16* a_hi = (__nv_bfloat16*)tmp;
    __nv_bfloat16* a_lo = a_hi + (size_t)MQ * DQ;
    __nv_bfloat16* w_hi = (__nv_bfloat16*)wsp;
    __nv_bfloat16* w_lo = w_hi + (size_t)N3Q * DQ;

    cudaFuncSetAttribute(col_attn_kernel,
                         cudaFuncAttributeMaxDynamicSharedMemorySize, 131072);
    cudaFuncSetAttribute(qkv_gemm_bf16,
                         cudaFuncAttributeMaxDynamicSharedMemorySize, MV2_SMEM);

    const int n4A = MQ * DQ / 4;     // 6291456
    const int n4B = N3Q * DQ / 4;    // 442368
    dim3 gemm_grid(N3Q / 128, MQ / 128);   // (18, 256)

    // --- row stage ---
    split_bf16<<<n4A / 256, 256>>>(x, a_hi, a_lo, n4A);
    split_bf16<<<n4B / 256, 256>>>(w_row, w_hi, w_lo, n4B);
    qkv_gemm_bf16<<<gemm_grid, 256, MV2_SMEM>>>(a_hi, a_lo, w_hi, w_lo, b_row, qkv);

    row_logits_part<<<dim3(4, 4, HQ * NSP), 256>>>(qkv, out1);
    softmax_row<<<HQ * LQ, 256>>>(out1, attn);
    row_av<<<dim3(4, HQ, SQ), 256>>>(attn, qkv, tmp);
    add_ln<<<MQ, 256>>>(x, tmp, g1, beta1, out1);

    // --- column stage ---
    split_bf16<<<n4A / 256, 256>>>(out1, a_hi, a_lo, n4A);
    split_bf16<<<n4B / 256, 256>>>(w_col, w_hi, w_lo, n4B);
    qkv_gemm_bf16<<<gemm_grid, 256, MV2_SMEM>>>(a_hi, a_lo, w_hi, w_lo, b_col, qkv);

    col_attn_kernel<<<dim3(LQ, HQ), 128, 131072>>>(qkv, tmp);
    add_ln<<<MQ, 256>>>(out1, tmp, g2, beta2, out);
}

// round 12
// speedup vs baseline: 1.9972x; 1.1661x over previous
#include <cuda_runtime.h>
#include <cuda_bf16.h>
#include <math.h>
#include <stdint.h>

// Shapes: B=1, S=128, L=256, D=768 (H=12, dh=64), M = S*L = 32768, 3D = 2304.
#define SQ   128
#define LQ   256
#define DQ   768
#define HQ   12
#define DHQ  64
#define MQ   (SQ * LQ)      // 32768
#define N3Q  (3 * DQ)       // 2304
#define NSP  8              // s-splits for row_logits

// ---------------- scratch (no cudaMalloc allowed) ----------------
__device__ float g_qkv[(size_t)MQ * N3Q];        // 302 MB
__device__ float g_attn[HQ * LQ * LQ];           // 3 MB
__device__ float g_tmp[(size_t)MQ * DQ];         // 100 MB: bf16 A hi/lo splits, then attn outputs
__device__ float g_out1[(size_t)MQ * DQ];        // 100 MB: row-logit partials, then LN1 output
__device__ float g_wsplit[2 * (size_t)N3Q * DQ]; // 14 MB : bf16 W hi/lo splits

// ================= helpers ==================
__device__ __forceinline__ void mma_bf16_16x8x16(float* c, const uint32_t* a, const uint32_t* b) {
    asm volatile(
        "mma.sync.aligned.m16n8k16.row.col.f32.bf16.bf16.f32 "
        "{%0,%1,%2,%3}, {%4,%5,%6,%7}, {%8,%9}, {%0,%1,%2,%3};"
        : "+f"(c[0]), "+f"(c[1]), "+f"(c[2]), "+f"(c[3])
        : "r"(a[0]), "r"(a[1]), "r"(a[2]), "r"(a[3]), "r"(b[0]), "r"(b[1]));
}

__device__ __forceinline__ uint32_t smem_u32(const void* p) {
    uint32_t a;
    asm("{ .reg .u64 t; cvta.to.shared.u64 t, %1; cvt.u32.u64 %0, t; }"
        : "=r"(a) : "l"(p));
    return a;
}

__device__ __forceinline__ void cpasync16(uint32_t dst, const void* src) {
    asm volatile("cp.async.cg.shared.global [%0], [%1], 16;" :: "r"(dst), "l"(src));
}
__device__ __forceinline__ void cp_commit() {
    asm volatile("cp.async.commit_group;" ::: "memory");
}
__device__ __forceinline__ void cp_wait1() {
    asm volatile("cp.async.wait_group 1;" ::: "memory");
}

// =================================================================
// Kernel 0: elementwise bf16 hi/lo split (precompute for mma GEMM)
// =================================================================
__global__ __launch_bounds__(256) void split_bf16(
    const float* __restrict__ in, __nv_bfloat16* __restrict__ hi,
    __nv_bfloat16* __restrict__ lo, int n4)
{
    int i = blockIdx.x * 256 + threadIdx.x;
    if (i >= n4) return;
    float4 v = ((const float4*)in)[i];
    __nv_bfloat16 h0 = __float2bfloat16_rn(v.x);
    __nv_bfloat16 h1 = __float2bfloat16_rn(v.y);
    __nv_bfloat16 h2 = __float2bfloat16_rn(v.z);
    __nv_bfloat16 h3 = __float2bfloat16_rn(v.w);
    __nv_bfloat16 l0 = __float2bfloat16_rn(v.x - __bfloat162float(h0));
    __nv_bfloat16 l1 = __float2bfloat16_rn(v.y - __bfloat162float(h1));
    __nv_bfloat16 l2 = __float2bfloat16_rn(v.z - __bfloat162float(h2));
    __nv_bfloat16 l3 = __float2bfloat16_rn(v.w - __bfloat162float(h3));
    uint32_t ph0 = ((uint32_t)__bfloat16_as_ushort(h1) << 16) | __bfloat16_as_ushort(h0);
    uint32_t ph1 = ((uint32_t)__bfloat16_as_ushort(h3) << 16) | __bfloat16_as_ushort(h2);
    uint32_t pl0 = ((uint32_t)__bfloat16_as_ushort(l1) << 16) | __bfloat16_as_ushort(l0);
    uint32_t pl1 = ((uint32_t)__bfloat16_as_ushort(l3) << 16) | __bfloat16_as_ushort(l2);
    ((uint2*)hi)[i] = make_uint2(ph0, ph1);
    ((uint2*)lo)[i] = make_uint2(pl0, pl1);
}

// =================================================================
// Kernel 1: bf16 x3-split GEMM: C[M,2304] = A*B^T + bias  (R11 winner)
// =================================================================
#define MV2_STAGE_B  40960
#define MV2_ARR_B    10240
#define MV2_SMEM     (2 * MV2_STAGE_B)

__global__ __launch_bounds__(256, 2) void qkv_gemm_bf16(
    const __nv_bfloat16* __restrict__ Ahi, const __nv_bfloat16* __restrict__ Alo,
    const __nv_bfloat16* __restrict__ Bhi, const __nv_bfloat16* __restrict__ Blo,
    const float* __restrict__ bias, float* __restrict__ C)
{
    extern __shared__ uint32_t sm2[];
    const int tid = threadIdx.x;
    const int m0 = blockIdx.y * 128;
    const int n0 = blockIdx.x * 128;
    const int w  = tid >> 5;
    const int l  = tid & 31;
    const int g  = l >> 2;
    const int q  = l & 3;
    const int wm = (w & 3) * 32;
    const int wn = (w >> 2) * 64;

    const int srow  = tid >> 1;
    const int shalf = tid & 1;
    const uint32_t smb = smem_u32(sm2);
    const uint32_t rowoff = (uint32_t)(srow * 20 + shalf * 8) * 4;

    const __nv_bfloat16* pAhi = Ahi + (size_t)(m0 + srow) * DQ + shalf * 16;
    const __nv_bfloat16* pAlo = Alo + (size_t)(m0 + srow) * DQ + shalf * 16;
    const __nv_bfloat16* pBhi = Bhi + (size_t)(n0 + srow) * DQ + shalf * 16;
    const __nv_bfloat16* pBlo = Blo + (size_t)(n0 + srow) * DQ + shalf * 16;

#define BF_ISSUE(ch2) do {                                                    \
    const uint32_t d = smb + ((ch2) & 1) * MV2_STAGE_B + rowoff;              \
    const __nv_bfloat16* sA0 = pAhi + (ch2) * 32;                             \
    const __nv_bfloat16* sA1 = pAlo + (ch2) * 32;                             \
    const __nv_bfloat16* sB0 = pBhi + (ch2) * 32;                             \
    const __nv_bfloat16* sB1 = pBlo + (ch2) * 32;                             \
    cpasync16(d,                 sA0); cpasync16(d + 16,                 sA0 + 8); \
    cpasync16(d + MV2_ARR_B,     sA1); cpasync16(d + MV2_ARR_B + 16,     sA1 + 8); \
    cpasync16(d + 2 * MV2_ARR_B, sB0); cpasync16(d + 2 * MV2_ARR_B + 16, sB0 + 8); \
    cpasync16(d + 3 * MV2_ARR_B, sB1); cpasync16(d + 3 * MV2_ARR_B + 16, sB1 + 8); \
} while (0)

    float c[2][8][4];
#pragma unroll
    for (int mi = 0; mi < 2; mi++)
#pragma unroll
        for (int ni = 0; ni < 8; ni++)
#pragma unroll
            for (int t = 0; t < 4; t++) c[mi][ni][t] = 0.f;

    BF_ISSUE(0); cp_commit();
    BF_ISSUE(1); cp_commit();

    const int NCH = DQ / 32;   // 24
    for (int ch = 0; ch < NCH; ch++) {
        cp_wait1();
        __syncthreads();

        const uint32_t* Sw  = sm2 + (ch & 1) * (MV2_STAGE_B / 4);
        const uint32_t* A_h = Sw;
        const uint32_t* A_l = Sw + 2560;
        const uint32_t* B_h = Sw + 5120;
        const uint32_t* B_l = Sw + 7680;

#pragma unroll
        for (int ks = 0; ks < 2; ks++) {
            const int ws = ks * 8;
            uint32_t ah[2][4], al[2][4], bh[8][2], bl[8][2];
#pragma unroll
            for (int mi = 0; mi < 2; mi++) {
                const int r = wm + mi * 16 + g;
                ah[mi][0] = A_h[r * 20 + ws + q];
                ah[mi][1] = A_h[(r + 8) * 20 + ws + q];
                ah[mi][2] = A_h[r * 20 + ws + q + 4];
                ah[mi][3] = A_h[(r + 8) * 20 + ws + q + 4];
                al[mi][0] = A_l[r * 20 + ws + q];
                al[mi][1] = A_l[(r + 8) * 20 + ws + q];
                al[mi][2] = A_l[r * 20 + ws + q + 4];
                al[mi][3] = A_l[(r + 8) * 20 + ws + q + 4];
            }
#pragma unroll
            for (int ni = 0; ni < 8; ni++) {
                const int rn = wn + ni * 8 + g;
                bh[ni][0] = B_h[rn * 20 + ws + q];
                bh[ni][1] = B_h[rn * 20 + ws + q + 4];
                bl[ni][0] = B_l[rn * 20 + ws + q];
                bl[ni][1] = B_l[rn * 20 + ws + q + 4];
            }
#pragma unroll
            for (int mi = 0; mi < 2; mi++)
#pragma unroll
                for (int ni = 0; ni < 8; ni++)
                    mma_bf16_16x8x16(c[mi][ni], ah[mi], bh[ni]);
#pragma unroll
            for (int mi = 0; mi < 2; mi++)
#pragma unroll
                for (int ni = 0; ni < 8; ni++)
                    mma_bf16_16x8x16(c[mi][ni], ah[mi], bl[ni]);
#pragma unroll
            for (int mi = 0; mi < 2; mi++)
#pragma unroll
                for (int ni = 0; ni < 8; ni++)
                    mma_bf16_16x8x16(c[mi][ni], al[mi], bh[ni]);
        }
        __syncthreads();
        if (ch + 2 < NCH) BF_ISSUE(ch + 2);
        cp_commit();
    }

#pragma unroll
    for (int ni = 0; ni < 8; ni++) {
        const int col = n0 + wn + ni * 8 + 2 * q;
        const float2 bv = *(const float2*)(bias + col);
#pragma unroll
        for (int mi = 0; mi < 2; mi++) {
            const int row0 = m0 + wm + mi * 16 + g;
            float2 o0 = make_float2(c[mi][ni][0] + bv.x, c[mi][ni][1] + bv.y);
            float2 o1 = make_float2(c[mi][ni][2] + bv.x, c[mi][ni][3] + bv.y);
            *(float2*)(C + (size_t)row0 * N3Q + col)       = o0;
            *(float2*)(C + (size_t)(row0 + 8) * N3Q + col) = o1;
        }
    }
#undef BF_ISSUE
}

// =================================================================
// Kernel 2: row logits partials, transposed smem (conflict-free LDS.128)
// part[sp,h,i,j] = sum_{s in chunk} sum_c Q[s,i,h,c] K[s,j,h,c]
// =================================================================
__global__ __launch_bounds__(256) void row_logits_part(
    const float* __restrict__ qkv, float* __restrict__ part)
{
    __shared__ float Qs[64][68];   // Qs[c][i]
    __shared__ float Ks[64][68];   // Ks[c][j]
    const int zz = blockIdx.z;
    const int h  = zz / NSP;
    const int sp = zz % NSP;
    const int i0 = blockIdx.y * 64;
    const int j0 = blockIdx.x * 64;
    const int tid  = threadIdx.x;
    const int lrow = tid >> 2;            // 0..63 : i or j index
    const int lcol = (tid & 3) << 4;      // 0,16,32,48 : c base
    const int tx = tid & 15;
    const int ty = tid >> 4;
    const int hb = h * DHQ;

    float acc[4][4];
#pragma unroll
    for (int i = 0; i < 4; i++)
#pragma unroll
        for (int j = 0; j < 4; j++) acc[i][j] = 0.f;

    const int s1 = sp * (SQ / NSP) + (SQ / NSP);
    for (int s = sp * (SQ / NSP); s < s1; s++) {
        const float* qrow = qkv + (size_t)(s * LQ + i0 + lrow) * N3Q + hb + lcol;
        const float* krow = qkv + (size_t)(s * LQ + j0 + lrow) * N3Q + DQ + hb + lcol;
#pragma unroll
        for (int u = 0; u < 16; u += 4) {
            float4 qa = *(const float4*)(qrow + u);
            Qs[lcol + u + 0][lrow] = qa.x; Qs[lcol + u + 1][lrow] = qa.y;
            Qs[lcol + u + 2][lrow] = qa.z; Qs[lcol + u + 3][lrow] = qa.w;
            float4 ka = *(const float4*)(krow + u);
            Ks[lcol + u + 0][lrow] = ka.x; Ks[lcol + u + 1][lrow] = ka.y;
            Ks[lcol + u + 2][lrow] = ka.z; Ks[lcol + u + 3][lrow] = ka.w;
        }
        __syncthreads();
#pragma unroll 16
        for (int cix = 0; cix < DHQ; cix++) {
            float4 af = *(const float4*)&Qs[cix][ty * 4];
            float4 bf = *(const float4*)&Ks[cix][tx * 4];
            const float a[4] = {af.x, af.y, af.z, af.w};
            const float b[4] = {bf.x, bf.y, bf.z, bf.w};
#pragma unroll
            for (int i = 0; i < 4; i++)
#pragma unroll
                for (int j = 0; j < 4; j++)
                    acc[i][j] += a[i] * b[j];
        }
        __syncthreads();
    }
    float* dst = part + ((size_t)(sp * HQ + h)) * LQ * LQ;
#pragma unroll
    for (int i = 0; i < 4; i++) {
        float4 v = make_float4(acc[i][0], acc[i][1], acc[i][2], acc[i][3]);
        *(float4*)&dst[(size_t)(i0 + ty * 4 + i) * LQ + j0 + tx * 4] = v;
    }
}

// =================================================================
// Kernel 3: reduce partials + softmax over last dim (256)
// =================================================================
__global__ __launch_bounds__(256) void softmax_row(
    const float* __restrict__ part, float* __restrict__ attn)
{
    const int row = blockIdx.x;          // h*256 + i
    const int h = row >> 8;
    const int i = row & 255;
    const int t = threadIdx.x;

    float v = 0.f;
#pragma unroll
    for (int sp = 0; sp < NSP; sp++)
        v += part[((size_t)(sp * HQ + h)) * LQ * LQ + (size_t)i * LQ + t];

    __shared__ float red[8];
    float m = v;
#pragma unroll
    for (int o = 16; o > 0; o >>= 1) m = fmaxf(m, __shfl_xor_sync(0xffffffffu, m, o));
    if ((t & 31) == 0) red[t >> 5] = m;
    __syncthreads();
    float mm = red[0];
#pragma unroll
    for (int k = 1; k < 8; k++) mm = fmaxf(mm, red[k]);
    __syncthreads();

    float e = expf(v - mm);
    float s = e;
#pragma unroll
    for (int o = 16; o > 0; o >>= 1) s += __shfl_xor_sync(0xffffffffu, s, o);
    if ((t & 31) == 0) red[t >> 5] = s;
    __syncthreads();
    float tot = 0.f;
#pragma unroll
    for (int k = 0; k < 8; k++) tot += red[k];

    attn[(size_t)row * LQ + t] = e / tot;
}

// =================================================================
// Kernel 4: row AV  out[s,i,h,d] = sum_j attn[h,i,j] V[s,j,h,d]
// (float4 V loads)
// =================================================================
__global__ __launch_bounds__(256) void row_av(
    const float* __restrict__ attn, const float* __restrict__ qkv,
    float* __restrict__ out)
{
    __shared__ float As[64][36];
    __shared__ float Vs[32][68];
    const int i0 = blockIdx.x * 64;
    const int h  = blockIdx.y;
    const int s  = blockIdx.z;
    const int tid = threadIdx.x;
    const int tx = tid & 15, ty = tid >> 4;
    const int a_row = tid >> 2, a_col = (tid & 3) << 3;
    const int v_row = tid >> 3, v_col = (tid & 7) << 3;

    float acc[4][4];
#pragma unroll
    for (int i = 0; i < 4; i++)
#pragma unroll
        for (int j = 0; j < 4; j++) acc[i][j] = 0.f;

    for (int jb = 0; jb < LQ; jb += 32) {
        const float* ap = attn + (size_t)h * LQ * LQ + (i0 + a_row) * LQ + jb + a_col;
        *(float4*)&As[a_row][a_col]     = *(const float4*)ap;
        *(float4*)&As[a_row][a_col + 4] = *(const float4*)(ap + 4);
        const float* vp = qkv + (size_t)(s * LQ + jb + v_row) * N3Q + 2 * DQ + h * DHQ + v_col;
        *(float4*)&Vs[v_row][v_col]     = *(const float4*)vp;
        *(float4*)&Vs[v_row][v_col + 4] = *(const float4*)(vp + 4);
        __syncthreads();
#pragma unroll 16
        for (int j = 0; j < 32; j++) {
            float a[4];
#pragma unroll
            for (int r = 0; r < 4; r++) a[r] = As[ty * 4 + r][j];
            float4 vf = *(const float4*)&Vs[j][tx * 4];
            const float v[4] = {vf.x, vf.y, vf.z, vf.w};
#pragma unroll
            for (int i = 0; i < 4; i++)
#pragma unroll
                for (int d = 0; d < 4; d++)
                    acc[i][d] += a[i] * v[d];
        }
        __syncthreads();
    }
#pragma unroll
    for (int i = 0; i < 4; i++) {
        float4 v = make_float4(acc[i][0], acc[i][1], acc[i][2], acc[i][3]);
        *(float4*)&out[(size_t)(s * LQ + i0 + ty * 4 + i) * DQ + h * DHQ + tx * 4] = v;
    }
}

// =================================================================
// Kernel 5: out[row,:] = LN(X[row,:] + R[row,:]) * g + b   (D=768)
// =================================================================
__global__ __launch_bounds__(256) void add_ln(
    const float* __restrict__ X, const float* __restrict__ R,
    const float* __restrict__ g, const float* __restrict__ b,
    float* __restrict__ out)
{
    const int row = blockIdx.x;
    const int t = threadIdx.x;
    const float* x = X + (size_t)row * DQ;
    const float* r = R + (size_t)row * DQ;
    float y0 = x[t]       + r[t];
    float y1 = x[t + 256] + r[t + 256];
    float y2 = x[t + 512] + r[t + 512];
    float s = y0 + y1 + y2;
    float qv = y0 * y0 + y1 * y1 + y2 * y2;

    __shared__ float ss[8], qq[8];
#pragma unroll
    for (int o = 16; o > 0; o >>= 1) {
        s  += __shfl_xor_sync(0xffffffffu, s, o);
        qv += __shfl_xor_sync(0xffffffffu, qv, o);
    }
    if ((t & 31) == 0) { ss[t >> 5] = s; qq[t >> 5] = qv; }
    __syncthreads();
    if (t < 32) {
        float s2 = (t < 8) ? ss[t] : 0.f;
        float q2 = (t < 8) ? qq[t] : 0.f;
#pragma unroll
        for (int o = 4; o > 0; o >>= 1) {
            s2 += __shfl_xor_sync(0xffffffffu, s2, o);
            q2 += __shfl_xor_sync(0xffffffffu, q2, o);
        }
        if (t == 0) { ss[0] = s2; qq[0] = q2; }
    }
    __syncthreads();
    const float invD = 1.f / (float)DQ;
    float mean = ss[0] * invD;
    float var  = qv = qq[0] * invD - mean * mean;
    float inv  = rsqrtf(var + 1e-5f);
    float* o = out + (size_t)row * DQ;
    o[t]       = (y0 - mean) * inv * g[t]       + b[t];
    o[t + 256] = (y1 - mean) * inv * g[t + 256] + b[t + 256];
    o[t + 512] = (y2 - mean) * inv * g[t + 512] + b[t + 512];
}

// =================================================================
// Kernel 7: column attention v3 — flash-style single pass, no P array.
// One CTA per (l,h); 128 threads; thread t owns query t.
// smem: Kt[j][c] + Vt[j][d], pad 68 -> 68KB -> 3 CTAs/SM.
// =================================================================
__global__ __launch_bounds__(128, 3) void col_attn_kernel(
    const float* __restrict__ qkv, float* __restrict__ out)
{
    __shared__ float Kt[128][68];
    __shared__ float Vt[128][68];

    const int l = blockIdx.x;
    const int h = blockIdx.y;
    const int t = threadIdx.x;
    const int base = l * N3Q + h * DHQ;

    // load K,V row t (coalesced gmem; 4-phase conflict-free STS.128)
    const float* krow = qkv + (size_t)(t * LQ) * N3Q + base + DQ;
    const float* vrow = krow + DQ;
#pragma unroll
    for (int c = 0; c < DHQ; c += 4) {
        *(float4*)&Kt[t][c] = *(const float4*)(krow + c);
        *(float4*)&Vt[t][c] = *(const float4*)(vrow + c);
    }
    float q[DHQ];
    const float* qrow = qkv + (size_t)(t * LQ) * N3Q + base;
#pragma unroll
    for (int c = 0; c < DHQ; c += 4) {
        float4 qf = *(const float4*)(qrow + c);
        q[c] = qf.x; q[c + 1] = qf.y; q[c + 2] = qf.z; q[c + 3] = qf.w;
    }

    float o[DHQ];
#pragma unroll
    for (int d = 0; d < DHQ; d++) o[d] = 0.f;
    float m = -3.4e38f, ssum = 0.f;
    __syncthreads();

    for (int j = 0; j < SQ; j++) {
        // logit: q_t . k_j   (broadcast float4 LDS)
        float a0 = 0.f, a1 = 0.f, a2 = 0.f, a3 = 0.f;
#pragma unroll
        for (int c = 0; c < DHQ; c += 4) {
            float4 k4 = *(const float4*)&Kt[j][c];
            a0 += q[c]     * k4.x;
            a1 += q[c + 1] * k4.y;
            a2 += q[c + 2] * k4.z;
            a3 += q[c + 3] * k4.w;
        }
        float sgm = (a0 + a1) + (a2 + a3);

        if (sgm > m) {
            float corr = expf(m - sgm);   // first iter: expf(-inf)=0
            ssum *= corr;
#pragma unroll
            for (int d = 0; d < DHQ; d++) o[d] *= corr;
            m = sgm;
        }
        float p = expf(sgm - m);
        ssum += p;
#pragma unroll
        for (int c = 0; c < DHQ; c += 4) {
            float4 v4 = *(const float4*)&Vt[j][c];
            o[c]     += p * v4.x;
            o[c + 1] += p * v4.y;
            o[c + 2] += p * v4.z;
            o[c + 3] += p * v4.w;
        }
    }

    const float inv = 1.f / ssum;
    float* orow = out + (size_t)(t * LQ + l) * DQ + h * DHQ;
#pragma unroll
    for (int d = 0; d < DHQ; d += 4) {
        float4 v = make_float4(o[d] * inv, o[d + 1] * inv, o[d + 2] * inv, o[d + 3] * inv);
        *(float4*)(orow + d) = v;
    }
}

// =================================================================
extern "C" void kernel_launch(void* const* d_in, const int* in_sizes, int n_in,
                              void* d_out, int out_size)
{
    const float* x     = (const float*)d_in[0];
    const float* w_row = (const float*)d_in[1];
    const float* b_row = (const float*)d_in[2];
    const float* w_col = (const float*)d_in[3];
    const float* b_col = (const float*)d_in[4];
    const float* g1    = (const float*)d_in[5];
    const float* beta1 = (const float*)d_in[6];
    const float* g2    = (const float*)d_in[7];
    const float* beta2 = (const float*)d_in[8];
    float* out = (float*)d_out;

    float *qkv, *attn, *tmp, *out1, *wsp;
    cudaGetSymbolAddress((void**)&qkv,  g_qkv);
    cudaGetSymbolAddress((void**)&attn, g_attn);
    cudaGetSymbolAddress((void**)&tmp,  g_tmp);
    cudaGetSymbolAddress((void**)&out1, g_out1);
    cudaGetSymbolAddress((void**)&wsp,  g_wsplit);

    __nv_bfloat16* a_hi = (__nv_bfloat16*)tmp;
    __nv_bfloat16* a_lo = a_hi + (size_t)MQ * DQ;
    __nv_bfloat16* w_hi = (__nv_bfloat16*)wsp;
    __nv_bfloat16* w_lo = w_hi + (size_t)N3Q * DQ;

    cudaFuncSetAttribute(qkv_gemm_bf16,
                         cudaFuncAttributeMaxDynamicSharedMemorySize, MV2_SMEM);

    const int n4A = MQ * DQ / 4;     // 6291456
    const int n4B = N3Q * DQ / 4;    // 442368
    dim3 gemm_grid(N3Q / 128, MQ / 128);   // (18, 256)

    // --- row stage ---
    split_bf16<<<n4A / 256, 256>>>(x, a_hi, a_lo, n4A);
    split_bf16<<<n4B / 256, 256>>>(w_row, w_hi, w_lo, n4B);
    qkv_gemm_bf16<<<gemm_grid, 256, MV2_SMEM>>>(a_hi, a_lo, w_hi, w_lo, b_row, qkv);

    row_logits_part<<<dim3(4, 4, HQ * NSP), 256>>>(qkv, out1);
    softmax_row<<<HQ * LQ, 256>>>(out1, attn);
    row_av<<<dim3(4, HQ, SQ), 256>>>(attn, qkv, tmp);
    add_ln<<<MQ, 256>>>(x, tmp, g1, beta1, out1);

    // --- column stage ---
    split_bf16<<<n4A / 256, 256>>>(out1, a_hi, a_lo, n4A);
    split_bf16<<<n4B / 256, 256>>>(w_col, w_hi, w_lo, n4B);
    qkv_gemm_bf16<<<gemm_grid, 256, MV2_SMEM>>>(a_hi, a_lo, w_hi, w_lo, b_col, qkv);

    col_attn_kernel<<<dim3(LQ, HQ), 128>>>(qkv, tmp);
    add_ln<<<MQ, 256>>>(out1, tmp, g2, beta2, out);
}

// round 13
// speedup vs baseline: 2.1445x; 1.0737x over previous
#include <cuda_runtime.h>
#include <cuda_bf16.h>
#include <math.h>
#include <stdint.h>

// Shapes: B=1, S=128, L=256, D=768 (H=12, dh=64), M = S*L = 32768, 3D = 2304.
#define SQ   128
#define LQ   256
#define DQ   768
#define HQ   12
#define DHQ  64
#define MQ   (SQ * LQ)      // 32768
#define N3Q  (3 * DQ)       // 2304
#define NSP  8              // k-splits for row_logits (1024 kk each)

// qksp layout: 4 arrays of [12][256][8192] bf16, stored as u32 pairs.
#define QK_U32   12582912           // u32 per array (12*256*4096)
#define QK_ELE   25165824           // bf16 elems per array

// ---------------- scratch (no cudaMalloc allowed) ----------------
__device__ float    g_qkv[(size_t)MQ * N3Q];        // 302 MB
__device__ float    g_attn[HQ * LQ * LQ];           // 3 MB
__device__ float    g_tmp[(size_t)MQ * DQ];         // 100 MB: bf16 A hi/lo splits, then attn outputs
__device__ float    g_out1[(size_t)MQ * DQ];        // 100 MB: row-logit partials, then LN1 output
__device__ float    g_wsplit[2 * (size_t)N3Q * DQ]; // 14 MB : bf16 W hi/lo splits
__device__ uint32_t g_qksp[4 * (size_t)QK_U32];     // 201 MB: Qhi|Qlo|Khi|Klo per-head K-major

// ================= helpers ==================
__device__ __forceinline__ void mma_bf16_16x8x16(float* c, const uint32_t* a, const uint32_t* b) {
    asm volatile(
        "mma.sync.aligned.m16n8k16.row.col.f32.bf16.bf16.f32 "
        "{%0,%1,%2,%3}, {%4,%5,%6,%7}, {%8,%9}, {%0,%1,%2,%3};"
        : "+f"(c[0]), "+f"(c[1]), "+f"(c[2]), "+f"(c[3])
        : "r"(a[0]), "r"(a[1]), "r"(a[2]), "r"(a[3]), "r"(b[0]), "r"(b[1]));
}

__device__ __forceinline__ uint32_t smem_u32(const void* p) {
    uint32_t a;
    asm("{ .reg .u64 t; cvta.to.shared.u64 t, %1; cvt.u32.u64 %0, t; }"
        : "=r"(a) : "l"(p));
    return a;
}

__device__ __forceinline__ void cpasync16(uint32_t dst, const void* src) {
    asm volatile("cp.async.cg.shared.global [%0], [%1], 16;" :: "r"(dst), "l"(src));
}
__device__ __forceinline__ void cp_commit() {
    asm volatile("cp.async.commit_group;" ::: "memory");
}
__device__ __forceinline__ void cp_wait1() {
    asm volatile("cp.async.wait_group 1;" ::: "memory");
}

__device__ __forceinline__ void pack_hi_lo(float x, float y, uint32_t& hi, uint32_t& lo) {
    __nv_bfloat16 hx = __float2bfloat16_rn(x);
    __nv_bfloat16 hy = __float2bfloat16_rn(y);
    __nv_bfloat16 lx = __float2bfloat16_rn(x - __bfloat162float(hx));
    __nv_bfloat16 ly = __float2bfloat16_rn(y - __bfloat162float(hy));
    hi = ((uint32_t)__bfloat16_as_ushort(hy) << 16) | __bfloat16_as_ushort(hx);
    lo = ((uint32_t)__bfloat16_as_ushort(ly) << 16) | __bfloat16_as_ushort(lx);
}

// =================================================================
// Kernel 0: elementwise bf16 hi/lo split (for the big QKV GEMMs)
// =================================================================
__global__ __launch_bounds__(256) void split_bf16(
    const float* __restrict__ in, __nv_bfloat16* __restrict__ hi,
    __nv_bfloat16* __restrict__ lo, int n4)
{
    int i = blockIdx.x * 256 + threadIdx.x;
    if (i >= n4) return;
    float4 v = ((const float4*)in)[i];
    uint32_t h0, l0, h1, l1;
    pack_hi_lo(v.x, v.y, h0, l0);
    pack_hi_lo(v.z, v.w, h1, l1);
    ((uint2*)hi)[i] = make_uint2(h0, h1);
    ((uint2*)lo)[i] = make_uint2(l0, l1);
}

// =================================================================
// Kernel 0b: split + transpose Q,K into per-head K-major bf16 hi/lo.
// Q'[h][i][kk] with kk = s*64+c. idx covers u32 outputs of Q then K.
// =================================================================
__global__ __launch_bounds__(256) void split_qk(
    const float* __restrict__ qkv, uint32_t* __restrict__ qksp)
{
    const int idx = blockIdx.x * 256 + threadIdx.x;   // 0 .. 2*QK_U32-1
    const int arr = idx / QK_U32;                      // 0=Q, 1=K
    const int r   = idx - arr * QK_U32;
    const int h   = r >> 20;                           // / (256*4096)
    const int rem = r & 0xFFFFF;
    const int i   = rem >> 12;                         // / 4096
    const int kk2 = rem & 4095;
    const int s   = kk2 >> 5;
    const int c   = (kk2 & 31) << 1;

    const float2 v = *(const float2*)(qkv + (size_t)(s * LQ + i) * N3Q
                                      + arr * DQ + h * DHQ + c);
    uint32_t hi, lo;
    pack_hi_lo(v.x, v.y, hi, lo);
    const uint32_t base = (uint32_t)arr * (2u * QK_U32);   // Q->0, K->2*QK_U32
    qksp[base + r]           = hi;
    qksp[base + QK_U32 + r]  = lo;
}

// =================================================================
// Kernel 1: bf16 x3-split GEMM: C[M,2304] = A*B^T + bias  (R11 winner)
// =================================================================
#define MV2_STAGE_B  40960
#define MV2_ARR_B    10240
#define MV2_SMEM     (2 * MV2_STAGE_B)

__global__ __launch_bounds__(256, 2) void qkv_gemm_bf16(
    const __nv_bfloat16* __restrict__ Ahi, const __nv_bfloat16* __restrict__ Alo,
    const __nv_bfloat16* __restrict__ Bhi, const __nv_bfloat16* __restrict__ Blo,
    const float* __restrict__ bias, float* __restrict__ C)
{
    extern __shared__ uint32_t sm2[];
    const int tid = threadIdx.x;
    const int m0 = blockIdx.y * 128;
    const int n0 = blockIdx.x * 128;
    const int w  = tid >> 5;
    const int l  = tid & 31;
    const int g  = l >> 2;
    const int q  = l & 3;
    const int wm = (w & 3) * 32;
    const int wn = (w >> 2) * 64;

    const int srow  = tid >> 1;
    const int shalf = tid & 1;
    const uint32_t smb = smem_u32(sm2);
    const uint32_t rowoff = (uint32_t)(srow * 20 + shalf * 8) * 4;

    const __nv_bfloat16* pAhi = Ahi + (size_t)(m0 + srow) * DQ + shalf * 16;
    const __nv_bfloat16* pAlo = Alo + (size_t)(m0 + srow) * DQ + shalf * 16;
    const __nv_bfloat16* pBhi = Bhi + (size_t)(n0 + srow) * DQ + shalf * 16;
    const __nv_bfloat16* pBlo = Blo + (size_t)(n0 + srow) * DQ + shalf * 16;

#define BF_ISSUE(ch2) do {                                                    \
    const uint32_t d = smb + ((ch2) & 1) * MV2_STAGE_B + rowoff;              \
    const __nv_bfloat16* sA0 = pAhi + (ch2) * 32;                             \
    const __nv_bfloat16* sA1 = pAlo + (ch2) * 32;                             \
    const __nv_bfloat16* sB0 = pBhi + (ch2) * 32;                             \
    const __nv_bfloat16* sB1 = pBlo + (ch2) * 32;                             \
    cpasync16(d,                 sA0); cpasync16(d + 16,                 sA0 + 8); \
    cpasync16(d + MV2_ARR_B,     sA1); cpasync16(d + MV2_ARR_B + 16,     sA1 + 8); \
    cpasync16(d + 2 * MV2_ARR_B, sB0); cpasync16(d + 2 * MV2_ARR_B + 16, sB0 + 8); \
    cpasync16(d + 3 * MV2_ARR_B, sB1); cpasync16(d + 3 * MV2_ARR_B + 16, sB1 + 8); \
} while (0)

    float c[2][8][4];
#pragma unroll
    for (int mi = 0; mi < 2; mi++)
#pragma unroll
        for (int ni = 0; ni < 8; ni++)
#pragma unroll
            for (int t = 0; t < 4; t++) c[mi][ni][t] = 0.f;

    BF_ISSUE(0); cp_commit();
    BF_ISSUE(1); cp_commit();

    const int NCH = DQ / 32;   // 24
    for (int ch = 0; ch < NCH; ch++) {
        cp_wait1();
        __syncthreads();

        const uint32_t* Sw  = sm2 + (ch & 1) * (MV2_STAGE_B / 4);
        const uint32_t* A_h = Sw;
        const uint32_t* A_l = Sw + 2560;
        const uint32_t* B_h = Sw + 5120;
        const uint32_t* B_l = Sw + 7680;

#pragma unroll
        for (int ks = 0; ks < 2; ks++) {
            const int ws = ks * 8;
            uint32_t ah[2][4], al[2][4], bh[8][2], bl[8][2];
#pragma unroll
            for (int mi = 0; mi < 2; mi++) {
                const int r = wm + mi * 16 + g;
                ah[mi][0] = A_h[r * 20 + ws + q];
                ah[mi][1] = A_h[(r + 8) * 20 + ws + q];
                ah[mi][2] = A_h[r * 20 + ws + q + 4];
                ah[mi][3] = A_h[(r + 8) * 20 + ws + q + 4];
                al[mi][0] = A_l[r * 20 + ws + q];
                al[mi][1] = A_l[(r + 8) * 20 + ws + q];
                al[mi][2] = A_l[r * 20 + ws + q + 4];
                al[mi][3] = A_l[(r + 8) * 20 + ws + q + 4];
            }
#pragma unroll
            for (int ni = 0; ni < 8; ni++) {
                const int rn = wn + ni * 8 + g;
                bh[ni][0] = B_h[rn * 20 + ws + q];
                bh[ni][1] = B_h[rn * 20 + ws + q + 4];
                bl[ni][0] = B_l[rn * 20 + ws + q];
                bl[ni][1] = B_l[rn * 20 + ws + q + 4];
            }
#pragma unroll
            for (int mi = 0; mi < 2; mi++)
#pragma unroll
                for (int ni = 0; ni < 8; ni++)
                    mma_bf16_16x8x16(c[mi][ni], ah[mi], bh[ni]);
#pragma unroll
            for (int mi = 0; mi < 2; mi++)
#pragma unroll
                for (int ni = 0; ni < 8; ni++)
                    mma_bf16_16x8x16(c[mi][ni], ah[mi], bl[ni]);
#pragma unroll
            for (int mi = 0; mi < 2; mi++)
#pragma unroll
                for (int ni = 0; ni < 8; ni++)
                    mma_bf16_16x8x16(c[mi][ni], al[mi], bh[ni]);
        }
        __syncthreads();
        if (ch + 2 < NCH) BF_ISSUE(ch + 2);
        cp_commit();
    }

#pragma unroll
    for (int ni = 0; ni < 8; ni++) {
        const int col = n0 + wn + ni * 8 + 2 * q;
        const float2 bv = *(const float2*)(bias + col);
#pragma unroll
        for (int mi = 0; mi < 2; mi++) {
            const int row0 = m0 + wm + mi * 16 + g;
            float2 o0 = make_float2(c[mi][ni][0] + bv.x, c[mi][ni][1] + bv.y);
            float2 o1 = make_float2(c[mi][ni][2] + bv.x, c[mi][ni][3] + bv.y);
            *(float2*)(C + (size_t)row0 * N3Q + col)       = o0;
            *(float2*)(C + (size_t)(row0 + 8) * N3Q + col) = o1;
        }
    }
#undef BF_ISSUE
}

// =================================================================
// Kernel 2: row logits via bf16 x3-split mma.
// part[sp,h,i,j] = sum_{kk in chunk sp} Q'[h,i,kk] K'[h,j,kk]
// Same structure as qkv_gemm_bf16; lda=8192, K=1024, no bias.
// =================================================================
__global__ __launch_bounds__(256, 2) void row_logits_mma(
    const uint32_t* __restrict__ qksp, float* __restrict__ part)
{
    extern __shared__ uint32_t sm2[];
    const int tid = threadIdx.x;
    const int h   = blockIdx.z >> 3;
    const int sp  = blockIdx.z & 7;
    const int i0 = blockIdx.y * 128;
    const int j0 = blockIdx.x * 128;
    const int w  = tid >> 5;
    const int l  = tid & 31;
    const int g  = l >> 2;
    const int q  = l & 3;
    const int wm = (w & 3) * 32;
    const int wn = (w >> 2) * 64;

    const int srow  = tid >> 1;
    const int shalf = tid & 1;
    const uint32_t smb = smem_u32(sm2);
    const uint32_t rowoff = (uint32_t)(srow * 20 + shalf * 8) * 4;

    const __nv_bfloat16* base = (const __nv_bfloat16*)qksp;
    const __nv_bfloat16* pAhi = base + (size_t)(h * 256 + i0 + srow) * 8192 + sp * 1024 + shalf * 16;
    const __nv_bfloat16* pAlo = pAhi + (size_t)QK_ELE;
    const __nv_bfloat16* pBhi = base + 2 * (size_t)QK_ELE
                              + (size_t)(h * 256 + j0 + srow) * 8192 + sp * 1024 + shalf * 16;
    const __nv_bfloat16* pBlo = pBhi + (size_t)QK_ELE;

#define RL_ISSUE(ch2) do {                                                    \
    const uint32_t d = smb + ((ch2) & 1) * MV2_STAGE_B + rowoff;              \
    const __nv_bfloat16* sA0 = pAhi + (ch2) * 32;                             \
    const __nv_bfloat16* sA1 = pAlo + (ch2) * 32;                             \
    const __nv_bfloat16* sB0 = pBhi + (ch2) * 32;                             \
    const __nv_bfloat16* sB1 = pBlo + (ch2) * 32;                             \
    cpasync16(d,                 sA0); cpasync16(d + 16,                 sA0 + 8); \
    cpasync16(d + MV2_ARR_B,     sA1); cpasync16(d + MV2_ARR_B + 16,     sA1 + 8); \
    cpasync16(d + 2 * MV2_ARR_B, sB0); cpasync16(d + 2 * MV2_ARR_B + 16, sB0 + 8); \
    cpasync16(d + 3 * MV2_ARR_B, sB1); cpasync16(d + 3 * MV2_ARR_B + 16, sB1 + 8); \
} while (0)

    float c[2][8][4];
#pragma unroll
    for (int mi = 0; mi < 2; mi++)
#pragma unroll
        for (int ni = 0; ni < 8; ni++)
#pragma unroll
            for (int t = 0; t < 4; t++) c[mi][ni][t] = 0.f;

    RL_ISSUE(0); cp_commit();
    RL_ISSUE(1); cp_commit();

    const int NCH = 1024 / 32;   // 32
    for (int ch = 0; ch < NCH; ch++) {
        cp_wait1();
        __syncthreads();

        const uint32_t* Sw  = sm2 + (ch & 1) * (MV2_STAGE_B / 4);
        const uint32_t* A_h = Sw;
        const uint32_t* A_l = Sw + 2560;
        const uint32_t* B_h = Sw + 5120;
        const uint32_t* B_l = Sw + 7680;

#pragma unroll
        for (int ks = 0; ks < 2; ks++) {
            const int ws = ks * 8;
            uint32_t ah[2][4], al[2][4], bh[8][2], bl[8][2];
#pragma unroll
            for (int mi = 0; mi < 2; mi++) {
                const int r = wm + mi * 16 + g;
                ah[mi][0] = A_h[r * 20 + ws + q];
                ah[mi][1] = A_h[(r + 8) * 20 + ws + q];
                ah[mi][2] = A_h[r * 20 + ws + q + 4];
                ah[mi][3] = A_h[(r + 8) * 20 + ws + q + 4];
                al[mi][0] = A_l[r * 20 + ws + q];
                al[mi][1] = A_l[(r + 8) * 20 + ws + q];
                al[mi][2] = A_l[r * 20 + ws + q + 4];
                al[mi][3] = A_l[(r + 8) * 20 + ws + q + 4];
            }
#pragma unroll
            for (int ni = 0; ni < 8; ni++) {
                const int rn = wn + ni * 8 + g;
                bh[ni][0] = B_h[rn * 20 + ws + q];
                bh[ni][1] = B_h[rn * 20 + ws + q + 4];
                bl[ni][0] = B_l[rn * 20 + ws + q];
                bl[ni][1] = B_l[rn * 20 + ws + q + 4];
            }
#pragma unroll
            for (int mi = 0; mi < 2; mi++)
#pragma unroll
                for (int ni = 0; ni < 8; ni++)
                    mma_bf16_16x8x16(c[mi][ni], ah[mi], bh[ni]);
#pragma unroll
            for (int mi = 0; mi < 2; mi++)
#pragma unroll
                for (int ni = 0; ni < 8; ni++)
                    mma_bf16_16x8x16(c[mi][ni], ah[mi], bl[ni]);
#pragma unroll
            for (int mi = 0; mi < 2; mi++)
#pragma unroll
                for (int ni = 0; ni < 8; ni++)
                    mma_bf16_16x8x16(c[mi][ni], al[mi], bh[ni]);
        }
        __syncthreads();
        if (ch + 2 < NCH) RL_ISSUE(ch + 2);
        cp_commit();
    }

    float* dst = part + (size_t)(sp * HQ + h) * (LQ * LQ);
#pragma unroll
    for (int ni = 0; ni < 8; ni++) {
        const int col = j0 + wn + ni * 8 + 2 * q;
#pragma unroll
        for (int mi = 0; mi < 2; mi++) {
            const int row0 = i0 + wm + mi * 16 + g;
            *(float2*)(dst + (size_t)row0 * LQ + col)       = make_float2(c[mi][ni][0], c[mi][ni][1]);
            *(float2*)(dst + (size_t)(row0 + 8) * LQ + col) = make_float2(c[mi][ni][2], c[mi][ni][3]);
        }
    }
#undef RL_ISSUE
}

// =================================================================
// Kernel 3: reduce partials + softmax over last dim (256)
// =================================================================
__global__ __launch_bounds__(256) void softmax_row(
    const float* __restrict__ part, float* __restrict__ attn)
{
    const int row = blockIdx.x;          // h*256 + i
    const int h = row >> 8;
    const int i = row & 255;
    const int t = threadIdx.x;

    float v = 0.f;
#pragma unroll
    for (int sp = 0; sp < NSP; sp++)
        v += part[((size_t)(sp * HQ + h)) * LQ * LQ + (size_t)i * LQ + t];

    __shared__ float red[8];
    float m = v;
#pragma unroll
    for (int o = 16; o > 0; o >>= 1) m = fmaxf(m, __shfl_xor_sync(0xffffffffu, m, o));
    if ((t & 31) == 0) red[t >> 5] = m;
    __syncthreads();
    float mm = red[0];
#pragma unroll
    for (int k = 1; k < 8; k++) mm = fmaxf(mm, red[k]);
    __syncthreads();

    float e = expf(v - mm);
    float s = e;
#pragma unroll
    for (int o = 16; o > 0; o >>= 1) s += __shfl_xor_sync(0xffffffffu, s, o);
    if ((t & 31) == 0) red[t >> 5] = s;
    __syncthreads();
    float tot = 0.f;
#pragma unroll
    for (int k = 0; k < 8; k++) tot += red[k];

    attn[(size_t)row * LQ + t] = e / tot;
}

// =================================================================
// Kernel 4: row AV  out[s,i,h,d] = sum_j attn[h,i,j] V[s,j,h,d]
// =================================================================
__global__ __launch_bounds__(256) void row_av(
    const float* __restrict__ attn, const float* __restrict__ qkv,
    float* __restrict__ out)
{
    __shared__ float As[64][36];
    __shared__ float Vs[32][68];
    const int i0 = blockIdx.x * 64;
    const int h  = blockIdx.y;
    const int s  = blockIdx.z;
    const int tid = threadIdx.x;
    const int tx = tid & 15, ty = tid >> 4;
    const int a_row = tid >> 2, a_col = (tid & 3) << 3;
    const int v_row = tid >> 3, v_col = (tid & 7) << 3;

    float acc[4][4];
#pragma unroll
    for (int i = 0; i < 4; i++)
#pragma unroll
        for (int j = 0; j < 4; j++) acc[i][j] = 0.f;

    for (int jb = 0; jb < LQ; jb += 32) {
        const float* ap = attn + (size_t)h * LQ * LQ + (i0 + a_row) * LQ + jb + a_col;
        *(float4*)&As[a_row][a_col]     = *(const float4*)ap;
        *(float4*)&As[a_row][a_col + 4] = *(const float4*)(ap + 4);
        const float* vp = qkv + (size_t)(s * LQ + jb + v_row) * N3Q + 2 * DQ + h * DHQ + v_col;
        *(float4*)&Vs[v_row][v_col]     = *(const float4*)vp;
        *(float4*)&Vs[v_row][v_col + 4] = *(const float4*)(vp + 4);
        __syncthreads();
#pragma unroll 16
        for (int j = 0; j < 32; j++) {
            float a[4];
#pragma unroll
            for (int r = 0; r < 4; r++) a[r] = As[ty * 4 + r][j];
            float4 vf = *(const float4*)&Vs[j][tx * 4];
            const float v[4] = {vf.x, vf.y, vf.z, vf.w};
#pragma unroll
            for (int i = 0; i < 4; i++)
#pragma unroll
                for (int d = 0; d < 4; d++)
                    acc[i][d] += a[i] * v[d];
        }
        __syncthreads();
    }
#pragma unroll
    for (int i = 0; i < 4; i++) {
        float4 v = make_float4(acc[i][0], acc[i][1], acc[i][2], acc[i][3]);
        *(float4*)&out[(size_t)(s * LQ + i0 + ty * 4 + i) * DQ + h * DHQ + tx * 4] = v;
    }
}

// =================================================================
// Kernel 5: out[row,:] = LN(X[row,:] + R[row,:]) * g + b   (D=768)
// =================================================================
__global__ __launch_bounds__(256) void add_ln(
    const float* __restrict__ X, const float* __restrict__ R,
    const float* __restrict__ g, const float* __restrict__ b,
    float* __restrict__ out)
{
    const int row = blockIdx.x;
    const int t = threadIdx.x;
    const float* x = X + (size_t)row * DQ;
    const float* r = R + (size_t)row * DQ;
    float y0 = x[t]       + r[t];
    float y1 = x[t + 256] + r[t + 256];
    float y2 = x[t + 512] + r[t + 512];
    float s = y0 + y1 + y2;
    float qv = y0 * y0 + y1 * y1 + y2 * y2;

    __shared__ float ss[8], qq[8];
#pragma unroll
    for (int o = 16; o > 0; o >>= 1) {
        s  += __shfl_xor_sync(0xffffffffu, s, o);
        qv += __shfl_xor_sync(0xffffffffu, qv, o);
    }
    if ((t & 31) == 0) { ss[t >> 5] = s; qq[t >> 5] = qv; }
    __syncthreads();
    if (t < 32) {
        float s2 = (t < 8) ? ss[t] : 0.f;
        float q2 = (t < 8) ? qq[t] : 0.f;
#pragma unroll
        for (int o = 4; o > 0; o >>= 1) {
            s2 += __shfl_xor_sync(0xffffffffu, s2, o);
            q2 += __shfl_xor_sync(0xffffffffu, q2, o);
        }
        if (t == 0) { ss[0] = s2; qq[0] = q2; }
    }
    __syncthreads();
    const float invD = 1.f / (float)DQ;
    float mean = ss[0] * invD;
    float var  = qq[0] * invD - mean * mean;
    float inv  = rsqrtf(var + 1e-5f);
    float* o = out + (size_t)row * DQ;
    o[t]       = (y0 - mean) * inv * g[t]       + b[t];
    o[t + 256] = (y1 - mean) * inv * g[t + 256] + b[t + 256];
    o[t + 512] = (y2 - mean) * inv * g[t + 512] + b[t + 512];
}

// =================================================================
// Kernel 7: column attention — flash-style single pass (R12 winner)
// =================================================================
__global__ __launch_bounds__(128, 3) void col_attn_kernel(
    const float* __restrict__ qkv, float* __restrict__ out)
{
    __shared__ float Kt[128][68];
    __shared__ float Vt[128][68];

    const int l = blockIdx.x;
    const int h = blockIdx.y;
    const int t = threadIdx.x;
    const int base = l * N3Q + h * DHQ;

    const float* krow = qkv + (size_t)(t * LQ) * N3Q + base + DQ;
    const float* vrow = krow + DQ;
#pragma unroll
    for (int c = 0; c < DHQ; c += 4) {
        *(float4*)&Kt[t][c] = *(const float4*)(krow + c);
        *(float4*)&Vt[t][c] = *(const float4*)(vrow + c);
    }
    float q[DHQ];
    const float* qrow = qkv + (size_t)(t * LQ) * N3Q + base;
#pragma unroll
    for (int c = 0; c < DHQ; c += 4) {
        float4 qf = *(const float4*)(qrow + c);
        q[c] = qf.x; q[c + 1] = qf.y; q[c + 2] = qf.z; q[c + 3] = qf.w;
    }

    float o[DHQ];
#pragma unroll
    for (int d = 0; d < DHQ; d++) o[d] = 0.f;
    float m = -3.4e38f, ssum = 0.f;
    __syncthreads();

    for (int j = 0; j < SQ; j++) {
        float a0 = 0.f, a1 = 0.f, a2 = 0.f, a3 = 0.f;
#pragma unroll
        for (int c = 0; c < DHQ; c += 4) {
            float4 k4 = *(const float4*)&Kt[j][c];
            a0 += q[c]     * k4.x;
            a1 += q[c + 1] * k4.y;
            a2 += q[c + 2] * k4.z;
            a3 += q[c + 3] * k4.w;
        }
        float sgm = (a0 + a1) + (a2 + a3);

        if (sgm > m) {
            float corr = expf(m - sgm);
            ssum *= corr;
#pragma unroll
            for (int d = 0; d < DHQ; d++) o[d] *= corr;
            m = sgm;
        }
        float p = expf(sgm - m);
        ssum += p;
#pragma unroll
        for (int c = 0; c < DHQ; c += 4) {
            float4 v4 = *(const float4*)&Vt[j][c];
            o[c]     += p * v4.x;
            o[c + 1] += p * v4.y;
            o[c + 2] += p * v4.z;
            o[c + 3] += p * v4.w;
        }
    }

    const float inv = 1.f / ssum;
    float* orow = out + (size_t)(t * LQ + l) * DQ + h * DHQ;
#pragma unroll
    for (int d = 0; d < DHQ; d += 4) {
        float4 v = make_float4(o[d] * inv, o[d + 1] * inv, o[d + 2] * inv, o[d + 3] * inv);
        *(float4*)(orow + d) = v;
    }
}

// =================================================================
extern "C" void kernel_launch(void* const* d_in, const int* in_sizes, int n_in,
                              void* d_out, int out_size)
{
    const float* x     = (const float*)d_in[0];
    const float* w_row = (const float*)d_in[1];
    const float* b_row = (const float*)d_in[2];
    const float* w_col = (const float*)d_in[3];
    const float* b_col = (const float*)d_in[4];
    const float* g1    = (const float*)d_in[5];
    const float* beta1 = (const float*)d_in[6];
    const float* g2    = (const float*)d_in[7];
    const float* beta2 = (const float*)d_in[8];
    float* out = (float*)d_out;

    float *qkv, *attn, *tmp, *out1, *wsp;
    uint32_t* qksp;
    cudaGetSymbolAddress((void**)&qkv,  g_qkv);
    cudaGetSymbolAddress((void**)&attn, g_attn);
    cudaGetSymbolAddress((void**)&tmp,  g_tmp);
    cudaGetSymbolAddress((void**)&out1, g_out1);
    cudaGetSymbolAddress((void**)&wsp,  g_wsplit);
    cudaGetSymbolAddress((void**)&qksp, g_qksp);

    __nv_bfloat16* a_hi = (__nv_bfloat16*)tmp;
    __nv_bfloat16* a_lo = a_hi + (size_t)MQ * DQ;
    __nv_bfloat16* w_hi = (__nv_bfloat16*)wsp;
    __nv_bfloat16* w_lo = w_hi + (size_t)N3Q * DQ;

    cudaFuncSetAttribute(qkv_gemm_bf16,
                         cudaFuncAttributeMaxDynamicSharedMemorySize, MV2_SMEM);
    cudaFuncSetAttribute(row_logits_mma,
                         cudaFuncAttributeMaxDynamicSharedMemorySize, MV2_SMEM);

    const int n4A = MQ * DQ / 4;     // 6291456
    const int n4B = N3Q * DQ / 4;    // 442368
    dim3 gemm_grid(N3Q / 128, MQ / 128);   // (18, 256)

    // --- row stage ---
    split_bf16<<<n4A / 256, 256>>>(x, a_hi, a_lo, n4A);
    split_bf16<<<n4B / 256, 256>>>(w_row, w_hi, w_lo, n4B);
    qkv_gemm_bf16<<<gemm_grid, 256, MV2_SMEM>>>(a_hi, a_lo, w_hi, w_lo, b_row, qkv);

    split_qk<<<2 * QK_U32 / 256, 256>>>(qkv, qksp);
    row_logits_mma<<<dim3(2, 2, HQ * NSP), 256, MV2_SMEM>>>(qksp, out1);
    softmax_row<<<HQ * LQ, 256>>>(out1, attn);
    row_av<<<dim3(4, HQ, SQ), 256>>>(attn, qkv, tmp);
    add_ln<<<MQ, 256>>>(x, tmp, g1, beta1, out1);

    // --- column stage ---
    split_bf16<<<n4A / 256, 256>>>(out1, a_hi, a_lo, n4A);
    split_bf16<<<n4B / 256, 256>>>(w_col, w_hi, w_lo, n4B);
    qkv_gemm_bf16<<<gemm_grid, 256, MV2_SMEM>>>(a_hi, a_lo, w_hi, w_lo, b_col, qkv);

    col_attn_kernel<<<dim3(LQ, HQ), 128>>>(qkv, tmp);
    add_ln<<<MQ, 256>>>(out1, tmp, g2, beta2, out);
}

// round 14
// speedup vs baseline: 2.2870x; 1.0665x over previous
#include <cuda_runtime.h>
#include <cuda_bf16.h>
#include <math.h>
#include <stdint.h>

// Shapes: B=1, S=128, L=256, D=768 (H=12, dh=64), M = S*L = 32768, 3D = 2304.
#define SQ   128
#define LQ   256
#define DQ   768
#define HQ   12
#define DHQ  64
#define MQ   (SQ * LQ)      // 32768
#define N3Q  (3 * DQ)       // 2304
#define NSP  8              // k-splits for row_logits (1024 kk each)

// qksp layout: 4 arrays of [12][256][8192] bf16, stored as u32 pairs.
#define QK_U32   12582912           // u32 per array (12*256*4096)
#define QK_ELE   25165824           // bf16 elems per array
#define AT_ELE   786432             // attn bf16 elems per array (12*256*256)

// ---------------- scratch (no cudaMalloc allowed) ----------------
__device__ float    g_qkv[(size_t)MQ * N3Q];        // 302 MB
__device__ float    g_attn[HQ * LQ * LQ];           // 3 MB
__device__ float    g_tmp[(size_t)MQ * DQ];         // 100 MB: bf16 A splits / row_av_mma out / attn out
__device__ float    g_out1[(size_t)MQ * DQ];        // 100 MB: row-logit partials, then LN1 output
__device__ float    g_wsplit[2 * (size_t)N3Q * DQ]; // 14 MB : W splits, then attn splits
__device__ uint32_t g_qksp[4 * (size_t)QK_U32];     // 201 MB: Q/K splits, then V'' splits

// ================= helpers ==================
__device__ __forceinline__ void mma_bf16_16x8x16(float* c, const uint32_t* a, const uint32_t* b) {
    asm volatile(
        "mma.sync.aligned.m16n8k16.row.col.f32.bf16.bf16.f32 "
        "{%0,%1,%2,%3}, {%4,%5,%6,%7}, {%8,%9}, {%0,%1,%2,%3};"
        : "+f"(c[0]), "+f"(c[1]), "+f"(c[2]), "+f"(c[3])
        : "r"(a[0]), "r"(a[1]), "r"(a[2]), "r"(a[3]), "r"(b[0]), "r"(b[1]));
}

__device__ __forceinline__ uint32_t smem_u32(const void* p) {
    uint32_t a;
    asm("{ .reg .u64 t; cvta.to.shared.u64 t, %1; cvt.u32.u64 %0, t; }"
        : "=r"(a) : "l"(p));
    return a;
}

__device__ __forceinline__ void cpasync16(uint32_t dst, const void* src) {
    asm volatile("cp.async.cg.shared.global [%0], [%1], 16;" :: "r"(dst), "l"(src));
}
__device__ __forceinline__ void cp_commit() {
    asm volatile("cp.async.commit_group;" ::: "memory");
}
__device__ __forceinline__ void cp_wait1() {
    asm volatile("cp.async.wait_group 1;" ::: "memory");
}

__device__ __forceinline__ void pack_hi_lo(float x, float y, uint32_t& hi, uint32_t& lo) {
    __nv_bfloat16 hx = __float2bfloat16_rn(x);
    __nv_bfloat16 hy = __float2bfloat16_rn(y);
    __nv_bfloat16 lx = __float2bfloat16_rn(x - __bfloat162float(hx));
    __nv_bfloat16 ly = __float2bfloat16_rn(y - __bfloat162float(hy));
    hi = ((uint32_t)__bfloat16_as_ushort(hy) << 16) | __bfloat16_as_ushort(hx);
    lo = ((uint32_t)__bfloat16_as_ushort(ly) << 16) | __bfloat16_as_ushort(lx);
}

// =================================================================
// Kernel 0: elementwise bf16 hi/lo split
// =================================================================
__global__ __launch_bounds__(256) void split_bf16(
    const float* __restrict__ in, __nv_bfloat16* __restrict__ hi,
    __nv_bfloat16* __restrict__ lo, int n4)
{
    int i = blockIdx.x * 256 + threadIdx.x;
    if (i >= n4) return;
    float4 v = ((const float4*)in)[i];
    uint32_t h0, l0, h1, l1;
    pack_hi_lo(v.x, v.y, h0, l0);
    pack_hi_lo(v.z, v.w, h1, l1);
    ((uint2*)hi)[i] = make_uint2(h0, h1);
    ((uint2*)lo)[i] = make_uint2(l0, l1);
}

// =================================================================
// Kernel 0b: split + transpose Q,K into per-head K-major bf16 hi/lo.
// =================================================================
__global__ __launch_bounds__(256) void split_qk(
    const float* __restrict__ qkv, uint32_t* __restrict__ qksp)
{
    const int idx = blockIdx.x * 256 + threadIdx.x;   // 0 .. 2*QK_U32-1
    const int arr = idx / QK_U32;                      // 0=Q, 1=K
    const int r   = idx - arr * QK_U32;
    const int h   = r >> 20;
    const int rem = r & 0xFFFFF;
    const int i   = rem >> 12;
    const int kk2 = rem & 4095;
    const int s   = kk2 >> 5;
    const int c   = (kk2 & 31) << 1;

    const float2 v = *(const float2*)(qkv + (size_t)(s * LQ + i) * N3Q
                                      + arr * DQ + h * DHQ + c);
    uint32_t hi, lo;
    pack_hi_lo(v.x, v.y, hi, lo);
    const uint32_t base = (uint32_t)arr * (2u * QK_U32);
    qksp[base + r]           = hi;
    qksp[base + QK_U32 + r]  = lo;
}

// =================================================================
// Kernel 0c: split + transpose V into V''[h][(s,d)][j] bf16 hi/lo.
// One CTA per (s,h): tile V[j 0..255][d 0..63] via smem.
// =================================================================
__global__ __launch_bounds__(256) void split_v(
    const float* __restrict__ qkv, uint32_t* __restrict__ vsp)
{
    extern __shared__ float T[];   // [64][258]
    const int s = blockIdx.x;
    const int h = blockIdx.y;
    const int t = threadIdx.x;

    // read: 16384 floats, coalesced over d
#pragma unroll
    for (int k = 0; k < 64; k++) {
        int idx = t + k * 256;
        int j = idx >> 6, d = idx & 63;
        T[d * 258 + j] = qkv[(size_t)(s * LQ + j) * N3Q + 2 * DQ + h * DHQ + d];
    }
    __syncthreads();

    // write: rows sd = s*64+d, 128 u32 per row (j pairs)
#pragma unroll
    for (int k = 0; k < 32; k++) {
        int idx = t + k * 256;
        int d = idx >> 7, j2 = idx & 127;
        uint32_t hi, lo;
        pack_hi_lo(T[d * 258 + 2 * j2], T[d * 258 + 2 * j2 + 1], hi, lo);
        const uint32_t off = (uint32_t)(h * 8192 + s * 64 + d) * 128 + j2;
        vsp[off]          = hi;
        vsp[QK_U32 + off] = lo;
    }
}

// =================================================================
// Kernel 1: bf16 x3-split GEMM: C[M,2304] = A*B^T + bias  (R11 winner)
// =================================================================
#define MV2_STAGE_B  40960
#define MV2_ARR_B    10240
#define MV2_SMEM     (2 * MV2_STAGE_B)

__global__ __launch_bounds__(256, 2) void qkv_gemm_bf16(
    const __nv_bfloat16* __restrict__ Ahi, const __nv_bfloat16* __restrict__ Alo,
    const __nv_bfloat16* __restrict__ Bhi, const __nv_bfloat16* __restrict__ Blo,
    const float* __restrict__ bias, float* __restrict__ C)
{
    extern __shared__ uint32_t sm2[];
    const int tid = threadIdx.x;
    const int m0 = blockIdx.y * 128;
    const int n0 = blockIdx.x * 128;
    const int w  = tid >> 5;
    const int l  = tid & 31;
    const int g  = l >> 2;
    const int q  = l & 3;
    const int wm = (w & 3) * 32;
    const int wn = (w >> 2) * 64;

    const int srow  = tid >> 1;
    const int shalf = tid & 1;
    const uint32_t smb = smem_u32(sm2);
    const uint32_t rowoff = (uint32_t)(srow * 20 + shalf * 8) * 4;

    const __nv_bfloat16* pAhi = Ahi + (size_t)(m0 + srow) * DQ + shalf * 16;
    const __nv_bfloat16* pAlo = Alo + (size_t)(m0 + srow) * DQ + shalf * 16;
    const __nv_bfloat16* pBhi = Bhi + (size_t)(n0 + srow) * DQ + shalf * 16;
    const __nv_bfloat16* pBlo = Blo + (size_t)(n0 + srow) * DQ + shalf * 16;

#define BF_ISSUE(ch2) do {                                                    \
    const uint32_t d = smb + ((ch2) & 1) * MV2_STAGE_B + rowoff;              \
    const __nv_bfloat16* sA0 = pAhi + (ch2) * 32;                             \
    const __nv_bfloat16* sA1 = pAlo + (ch2) * 32;                             \
    const __nv_bfloat16* sB0 = pBhi + (ch2) * 32;                             \
    const __nv_bfloat16* sB1 = pBlo + (ch2) * 32;                             \
    cpasync16(d,                 sA0); cpasync16(d + 16,                 sA0 + 8); \
    cpasync16(d + MV2_ARR_B,     sA1); cpasync16(d + MV2_ARR_B + 16,     sA1 + 8); \
    cpasync16(d + 2 * MV2_ARR_B, sB0); cpasync16(d + 2 * MV2_ARR_B + 16, sB0 + 8); \
    cpasync16(d + 3 * MV2_ARR_B, sB1); cpasync16(d + 3 * MV2_ARR_B + 16, sB1 + 8); \
} while (0)

    float c[2][8][4];
#pragma unroll
    for (int mi = 0; mi < 2; mi++)
#pragma unroll
        for (int ni = 0; ni < 8; ni++)
#pragma unroll
            for (int t = 0; t < 4; t++) c[mi][ni][t] = 0.f;

    BF_ISSUE(0); cp_commit();
    BF_ISSUE(1); cp_commit();

    const int NCH = DQ / 32;   // 24
    for (int ch = 0; ch < NCH; ch++) {
        cp_wait1();
        __syncthreads();

        const uint32_t* Sw  = sm2 + (ch & 1) * (MV2_STAGE_B / 4);
        const uint32_t* A_h = Sw;
        const uint32_t* A_l = Sw + 2560;
        const uint32_t* B_h = Sw + 5120;
        const uint32_t* B_l = Sw + 7680;

#pragma unroll
        for (int ks = 0; ks < 2; ks++) {
            const int ws = ks * 8;
            uint32_t ah[2][4], al[2][4], bh[8][2], bl[8][2];
#pragma unroll
            for (int mi = 0; mi < 2; mi++) {
                const int r = wm + mi * 16 + g;
                ah[mi][0] = A_h[r * 20 + ws + q];
                ah[mi][1] = A_h[(r + 8) * 20 + ws + q];
                ah[mi][2] = A_h[r * 20 + ws + q + 4];
                ah[mi][3] = A_h[(r + 8) * 20 + ws + q + 4];
                al[mi][0] = A_l[r * 20 + ws + q];
                al[mi][1] = A_l[(r + 8) * 20 + ws + q];
                al[mi][2] = A_l[r * 20 + ws + q + 4];
                al[mi][3] = A_l[(r + 8) * 20 + ws + q + 4];
            }
#pragma unroll
            for (int ni = 0; ni < 8; ni++) {
                const int rn = wn + ni * 8 + g;
                bh[ni][0] = B_h[rn * 20 + ws + q];
                bh[ni][1] = B_h[rn * 20 + ws + q + 4];
                bl[ni][0] = B_l[rn * 20 + ws + q];
                bl[ni][1] = B_l[rn * 20 + ws + q + 4];
            }
#pragma unroll
            for (int mi = 0; mi < 2; mi++)
#pragma unroll
                for (int ni = 0; ni < 8; ni++)
                    mma_bf16_16x8x16(c[mi][ni], ah[mi], bh[ni]);
#pragma unroll
            for (int mi = 0; mi < 2; mi++)
#pragma unroll
                for (int ni = 0; ni < 8; ni++)
                    mma_bf16_16x8x16(c[mi][ni], ah[mi], bl[ni]);
#pragma unroll
            for (int mi = 0; mi < 2; mi++)
#pragma unroll
                for (int ni = 0; ni < 8; ni++)
                    mma_bf16_16x8x16(c[mi][ni], al[mi], bh[ni]);
        }
        __syncthreads();
        if (ch + 2 < NCH) BF_ISSUE(ch + 2);
        cp_commit();
    }

#pragma unroll
    for (int ni = 0; ni < 8; ni++) {
        const int col = n0 + wn + ni * 8 + 2 * q;
        const float2 bv = *(const float2*)(bias + col);
#pragma unroll
        for (int mi = 0; mi < 2; mi++) {
            const int row0 = m0 + wm + mi * 16 + g;
            float2 o0 = make_float2(c[mi][ni][0] + bv.x, c[mi][ni][1] + bv.y);
            float2 o1 = make_float2(c[mi][ni][2] + bv.x, c[mi][ni][3] + bv.y);
            *(float2*)(C + (size_t)row0 * N3Q + col)       = o0;
            *(float2*)(C + (size_t)(row0 + 8) * N3Q + col) = o1;
        }
    }
#undef BF_ISSUE
}

// =================================================================
// Generic mma tile kernel body (macro): both operands K-major, lda=ldb=LDK.
// Emits the chunked 3-term bf16 split loop and leaves c[][][] filled.
// =================================================================
#define MMA_TILE_BODY(pAhi_, pAlo_, pBhi_, pBlo_, NCH_)                        \
    float c[2][8][4];                                                          \
    _Pragma("unroll")                                                          \
    for (int mi = 0; mi < 2; mi++)                                             \
        _Pragma("unroll")                                                      \
        for (int ni = 0; ni < 8; ni++)                                         \
            _Pragma("unroll")                                                  \
            for (int t2 = 0; t2 < 4; t2++) c[mi][ni][t2] = 0.f;                \
    { const uint32_t d0 = smb + rowoff;                                        \
      cpasync16(d0, pAhi_); cpasync16(d0 + 16, pAhi_ + 8);                     \
      cpasync16(d0 + MV2_ARR_B, pAlo_); cpasync16(d0 + MV2_ARR_B + 16, pAlo_ + 8); \
      cpasync16(d0 + 2*MV2_ARR_B, pBhi_); cpasync16(d0 + 2*MV2_ARR_B + 16, pBhi_ + 8); \
      cpasync16(d0 + 3*MV2_ARR_B, pBlo_); cpasync16(d0 + 3*MV2_ARR_B + 16, pBlo_ + 8); } \
    cp_commit();                                                               \
    { const uint32_t d1 = smb + MV2_STAGE_B + rowoff;                          \
      cpasync16(d1, pAhi_ + 32); cpasync16(d1 + 16, pAhi_ + 40);               \
      cpasync16(d1 + MV2_ARR_B, pAlo_ + 32); cpasync16(d1 + MV2_ARR_B + 16, pAlo_ + 40); \
      cpasync16(d1 + 2*MV2_ARR_B, pBhi_ + 32); cpasync16(d1 + 2*MV2_ARR_B + 16, pBhi_ + 40); \
      cpasync16(d1 + 3*MV2_ARR_B, pBlo_ + 32); cpasync16(d1 + 3*MV2_ARR_B + 16, pBlo_ + 40); } \
    cp_commit();                                                               \
    for (int ch = 0; ch < (NCH_); ch++) {                                      \
        cp_wait1();                                                            \
        __syncthreads();                                                       \
        const uint32_t* Sw  = sm2 + (ch & 1) * (MV2_STAGE_B / 4);              \
        const uint32_t* A_h = Sw;                                              \
        const uint32_t* A_l = Sw + 2560;                                       \
        const uint32_t* B_h = Sw + 5120;                                       \
        const uint32_t* B_l = Sw + 7680;                                       \
        _Pragma("unroll")                                                      \
        for (int ks = 0; ks < 2; ks++) {                                       \
            const int ws = ks * 8;                                             \
            uint32_t ah[2][4], al[2][4], bh[8][2], bl[8][2];                   \
            _Pragma("unroll")                                                  \
            for (int mi = 0; mi < 2; mi++) {                                   \
                const int r = wm + mi * 16 + g;                                \
                ah[mi][0] = A_h[r * 20 + ws + q];                              \
                ah[mi][1] = A_h[(r + 8) * 20 + ws + q];                        \
                ah[mi][2] = A_h[r * 20 + ws + q + 4];                          \
                ah[mi][3] = A_h[(r + 8) * 20 + ws + q + 4];                    \
                al[mi][0] = A_l[r * 20 + ws + q];                              \
                al[mi][1] = A_l[(r + 8) * 20 + ws + q];                        \
                al[mi][2] = A_l[r * 20 + ws + q + 4];                          \
                al[mi][3] = A_l[(r + 8) * 20 + ws + q + 4];                    \
            }                                                                  \
            _Pragma("unroll")                                                  \
            for (int ni = 0; ni < 8; ni++) {                                   \
                const int rn = wn + ni * 8 + g;                                \
                bh[ni][0] = B_h[rn * 20 + ws + q];                             \
                bh[ni][1] = B_h[rn * 20 + ws + q + 4];                         \
                bl[ni][0] = B_l[rn * 20 + ws + q];                             \
                bl[ni][1] = B_l[rn * 20 + ws + q + 4];                         \
            }                                                                  \
            _Pragma("unroll")                                                  \
            for (int mi = 0; mi < 2; mi++)                                     \
                _Pragma("unroll")                                              \
                for (int ni = 0; ni < 8; ni++)                                 \
                    mma_bf16_16x8x16(c[mi][ni], ah[mi], bh[ni]);               \
            _Pragma("unroll")                                                  \
            for (int mi = 0; mi < 2; mi++)                                     \
                _Pragma("unroll")                                              \
                for (int ni = 0; ni < 8; ni++)                                 \
                    mma_bf16_16x8x16(c[mi][ni], ah[mi], bl[ni]);               \
            _Pragma("unroll")                                                  \
            for (int mi = 0; mi < 2; mi++)                                     \
                _Pragma("unroll")                                              \
                for (int ni = 0; ni < 8; ni++)                                 \
                    mma_bf16_16x8x16(c[mi][ni], al[mi], bh[ni]);               \
        }                                                                      \
        __syncthreads();                                                       \
        if (ch + 2 < (NCH_)) {                                                 \
            const uint32_t dn = smb + ((ch + 2) & 1) * MV2_STAGE_B + rowoff;   \
            const __nv_bfloat16* nA0 = pAhi_ + (ch + 2) * 32;                  \
            const __nv_bfloat16* nA1 = pAlo_ + (ch + 2) * 32;                  \
            const __nv_bfloat16* nB0 = pBhi_ + (ch + 2) * 32;                  \
            const __nv_bfloat16* nB1 = pBlo_ + (ch + 2) * 32;                  \
            cpasync16(dn, nA0); cpasync16(dn + 16, nA0 + 8);                   \
            cpasync16(dn + MV2_ARR_B, nA1); cpasync16(dn + MV2_ARR_B + 16, nA1 + 8); \
            cpasync16(dn + 2*MV2_ARR_B, nB0); cpasync16(dn + 2*MV2_ARR_B + 16, nB0 + 8); \
            cpasync16(dn + 3*MV2_ARR_B, nB1); cpasync16(dn + 3*MV2_ARR_B + 16, nB1 + 8); \
        }                                                                      \
        cp_commit();                                                           \
    }

// =================================================================
// Kernel 2: row logits via bf16 x3-split mma.
// =================================================================
__global__ __launch_bounds__(256, 2) void row_logits_mma(
    const uint32_t* __restrict__ qksp, float* __restrict__ part)
{
    extern __shared__ uint32_t sm2[];
    const int tid = threadIdx.x;
    const int h   = blockIdx.z >> 3;
    const int sp  = blockIdx.z & 7;
    const int i0 = blockIdx.y * 128;
    const int j0 = blockIdx.x * 128;
    const int w  = tid >> 5;
    const int l  = tid & 31;
    const int g  = l >> 2;
    const int q  = l & 3;
    const int wm = (w & 3) * 32;
    const int wn = (w >> 2) * 64;
    const int srow  = tid >> 1;
    const int shalf = tid & 1;
    const uint32_t smb = smem_u32(sm2);
    const uint32_t rowoff = (uint32_t)(srow * 20 + shalf * 8) * 4;

    const __nv_bfloat16* base = (const __nv_bfloat16*)qksp;
    const __nv_bfloat16* pAhi = base + (size_t)(h * 256 + i0 + srow) * 8192 + sp * 1024 + shalf * 16;
    const __nv_bfloat16* pAlo = pAhi + (size_t)QK_ELE;
    const __nv_bfloat16* pBhi = base + 2 * (size_t)QK_ELE
                              + (size_t)(h * 256 + j0 + srow) * 8192 + sp * 1024 + shalf * 16;
    const __nv_bfloat16* pBlo = pBhi + (size_t)QK_ELE;

    MMA_TILE_BODY(pAhi, pAlo, pBhi, pBlo, 32)

    float* dst = part + (size_t)(sp * HQ + h) * (LQ * LQ);
#pragma unroll
    for (int ni = 0; ni < 8; ni++) {
        const int col = j0 + wn + ni * 8 + 2 * q;
#pragma unroll
        for (int mi = 0; mi < 2; mi++) {
            const int row0 = i0 + wm + mi * 16 + g;
            *(float2*)(dst + (size_t)row0 * LQ + col)       = make_float2(c[mi][ni][0], c[mi][ni][1]);
            *(float2*)(dst + (size_t)(row0 + 8) * LQ + col) = make_float2(c[mi][ni][2], c[mi][ni][3]);
        }
    }
}

// =================================================================
// Kernel 2b: row AV via mma: out'[h][i][sd] = sum_j attn[h,i,j] V''[h][sd][j]
// =================================================================
__global__ __launch_bounds__(256, 2) void row_av_mma(
    const uint32_t* __restrict__ atsp, const uint32_t* __restrict__ vsp,
    float* __restrict__ outp)
{
    extern __shared__ uint32_t sm2[];
    const int tid = threadIdx.x;
    const int h  = blockIdx.z;
    const int i0 = blockIdx.y * 128;
    const int n0 = blockIdx.x * 128;
    const int w  = tid >> 5;
    const int l  = tid & 31;
    const int g  = l >> 2;
    const int q  = l & 3;
    const int wm = (w & 3) * 32;
    const int wn = (w >> 2) * 64;
    const int srow  = tid >> 1;
    const int shalf = tid & 1;
    const uint32_t smb = smem_u32(sm2);
    const uint32_t rowoff = (uint32_t)(srow * 20 + shalf * 8) * 4;

    const __nv_bfloat16* abase = (const __nv_bfloat16*)atsp;
    const __nv_bfloat16* vbase = (const __nv_bfloat16*)vsp;
    const __nv_bfloat16* pAhi = abase + (size_t)(h * 256 + i0 + srow) * 256 + shalf * 16;
    const __nv_bfloat16* pAlo = pAhi + (size_t)AT_ELE;
    const __nv_bfloat16* pBhi = vbase + (size_t)(h * 8192 + n0 + srow) * 256 + shalf * 16;
    const __nv_bfloat16* pBlo = pBhi + (size_t)QK_ELE;

    MMA_TILE_BODY(pAhi, pAlo, pBhi, pBlo, 8)

    float* dst = outp + (size_t)(h * 256) * 8192;
#pragma unroll
    for (int ni = 0; ni < 8; ni++) {
        const int col = n0 + wn + ni * 8 + 2 * q;
#pragma unroll
        for (int mi = 0; mi < 2; mi++) {
            const int row0 = i0 + wm + mi * 16 + g;
            *(float2*)(dst + (size_t)row0 * 8192 + col)       = make_float2(c[mi][ni][0], c[mi][ni][1]);
            *(float2*)(dst + (size_t)(row0 + 8) * 8192 + col) = make_float2(c[mi][ni][2], c[mi][ni][3]);
        }
    }
}

// =================================================================
// Kernel 3: reduce partials + softmax over last dim (256)
// =================================================================
__global__ __launch_bounds__(256) void softmax_row(
    const float* __restrict__ part, float* __restrict__ attn)
{
    const int row = blockIdx.x;          // h*256 + i
    const int h = row >> 8;
    const int i = row & 255;
    const int t = threadIdx.x;

    float v = 0.f;
#pragma unroll
    for (int sp = 0; sp < NSP; sp++)
        v += part[((size_t)(sp * HQ + h)) * LQ * LQ + (size_t)i * LQ + t];

    __shared__ float red[8];
    float m = v;
#pragma unroll
    for (int o = 16; o > 0; o >>= 1) m = fmaxf(m, __shfl_xor_sync(0xffffffffu, m, o));
    if ((t & 31) == 0) red[t >> 5] = m;
    __syncthreads();
    float mm = red[0];
#pragma unroll
    for (int k = 1; k < 8; k++) mm = fmaxf(mm, red[k]);
    __syncthreads();

    float e = expf(v - mm);
    float s = e;
#pragma unroll
    for (int o = 16; o > 0; o >>= 1) s += __shfl_xor_sync(0xffffffffu, s, o);
    if ((t & 31) == 0) red[t >> 5] = s;
    __syncthreads();
    float tot = 0.f;
#pragma unroll
    for (int k = 0; k < 8; k++) tot += red[k];

    attn[(size_t)row * LQ + t] = e / tot;
}

// =================================================================
// Kernel 5: out[row,:] = LN(X[row,:] + R[row,:]) * g + b   (D=768)
// =================================================================
__global__ __launch_bounds__(256) void add_ln(
    const float* __restrict__ X, const float* __restrict__ R,
    const float* __restrict__ g, const float* __restrict__ b,
    float* __restrict__ out)
{
    const int row = blockIdx.x;
    const int t = threadIdx.x;
    const float* x = X + (size_t)row * DQ;
    const float* r = R + (size_t)row * DQ;
    float y0 = x[t]       + r[t];
    float y1 = x[t + 256] + r[t + 256];
    float y2 = x[t + 512] + r[t + 512];
    float s = y0 + y1 + y2;
    float qv = y0 * y0 + y1 * y1 + y2 * y2;

    __shared__ float ss[8], qq[8];
#pragma unroll
    for (int o = 16; o > 0; o >>= 1) {
        s  += __shfl_xor_sync(0xffffffffu, s, o);
        qv += __shfl_xor_sync(0xffffffffu, qv, o);
    }
    if ((t & 31) == 0) { ss[t >> 5] = s; qq[t >> 5] = qv; }
    __syncthreads();
    if (t < 32) {
        float s2 = (t < 8) ? ss[t] : 0.f;
        float q2 = (t < 8) ? qq[t] : 0.f;
#pragma unroll
        for (int o = 4; o > 0; o >>= 1) {
            s2 += __shfl_xor_sync(0xffffffffu, s2, o);
            q2 += __shfl_xor_sync(0xffffffffu, q2, o);
        }
        if (t == 0) { ss[0] = s2; qq[0] = q2; }
    }
    __syncthreads();
    const float invD = 1.f / (float)DQ;
    float mean = ss[0] * invD;
    float var  = qq[0] * invD - mean * mean;
    float inv  = rsqrtf(var + 1e-5f);
    float* o = out + (size_t)row * DQ;
    o[t]       = (y0 - mean) * inv * g[t]       + b[t];
    o[t + 256] = (y1 - mean) * inv * g[t + 256] + b[t + 256];
    o[t + 512] = (y2 - mean) * inv * g[t + 512] + b[t + 512];
}

// =================================================================
// Kernel 5b: add_ln reading residual from permuted [h][i][sd] layout.
// =================================================================
__global__ __launch_bounds__(256) void add_ln_perm(
    const float* __restrict__ X, const float* __restrict__ Rp,
    const float* __restrict__ g, const float* __restrict__ b,
    float* __restrict__ out)
{
    const int row = blockIdx.x;          // s*256 + i
    const int s = row >> 8;
    const int i = row & 255;
    const int t = threadIdx.x;
    const float* x = X + (size_t)row * DQ;

    float y[3];
#pragma unroll
    for (int u = 0; u < 3; u++) {
        const int cc = t + u * 256;
        const int h = cc >> 6, d = cc & 63;
        y[u] = x[cc] + Rp[((size_t)(h * 256 + i)) * 8192 + s * 64 + d];
    }
    float sm = y[0] + y[1] + y[2];
    float qv = y[0] * y[0] + y[1] * y[1] + y[2] * y[2];

    __shared__ float ss[8], qq[8];
#pragma unroll
    for (int o = 16; o > 0; o >>= 1) {
        sm += __shfl_xor_sync(0xffffffffu, sm, o);
        qv += __shfl_xor_sync(0xffffffffu, qv, o);
    }
    if ((t & 31) == 0) { ss[t >> 5] = sm; qq[t >> 5] = qv; }
    __syncthreads();
    if (t < 32) {
        float s2 = (t < 8) ? ss[t] : 0.f;
        float q2 = (t < 8) ? qq[t] : 0.f;
#pragma unroll
        for (int o = 4; o > 0; o >>= 1) {
            s2 += __shfl_xor_sync(0xffffffffu, s2, o);
            q2 += __shfl_xor_sync(0xffffffffu, q2, o);
        }
        if (t == 0) { ss[0] = s2; qq[0] = q2; }
    }
    __syncthreads();
    const float invD = 1.f / (float)DQ;
    float mean = ss[0] * invD;
    float var  = qq[0] * invD - mean * mean;
    float inv  = rsqrtf(var + 1e-5f);
    float* o = out + (size_t)row * DQ;
#pragma unroll
    for (int u = 0; u < 3; u++) {
        const int cc = t + u * 256;
        o[cc] = (y[u] - mean) * inv * g[cc] + b[cc];
    }
}

// =================================================================
// Kernel 7: column attention — flash-style single pass (R12 winner)
// =================================================================
__global__ __launch_bounds__(128, 3) void col_attn_kernel(
    const float* __restrict__ qkv, float* __restrict__ out)
{
    __shared__ float Kt[128][68];
    __shared__ float Vt[128][68];

    const int l = blockIdx.x;
    const int h = blockIdx.y;
    const int t = threadIdx.x;
    const int base = l * N3Q + h * DHQ;

    const float* krow = qkv + (size_t)(t * LQ) * N3Q + base + DQ;
    const float* vrow = krow + DQ;
#pragma unroll
    for (int c = 0; c < DHQ; c += 4) {
        *(float4*)&Kt[t][c] = *(const float4*)(krow + c);
        *(float4*)&Vt[t][c] = *(const float4*)(vrow + c);
    }
    float q[DHQ];
    const float* qrow = qkv + (size_t)(t * LQ) * N3Q + base;
#pragma unroll
    for (int c = 0; c < DHQ; c += 4) {
        float4 qf = *(const float4*)(qrow + c);
        q[c] = qf.x; q[c + 1] = qf.y; q[c + 2] = qf.z; q[c + 3] = qf.w;
    }

    float o[DHQ];
#pragma unroll
    for (int d = 0; d < DHQ; d++) o[d] = 0.f;
    float m = -3.4e38f, ssum = 0.f;
    __syncthreads();

    for (int j = 0; j < SQ; j++) {
        float a0 = 0.f, a1 = 0.f, a2 = 0.f, a3 = 0.f;
#pragma unroll
        for (int c = 0; c < DHQ; c += 4) {
            float4 k4 = *(const float4*)&Kt[j][c];
            a0 += q[c]     * k4.x;
            a1 += q[c + 1] * k4.y;
            a2 += q[c + 2] * k4.z;
            a3 += q[c + 3] * k4.w;
        }
        float sgm = (a0 + a1) + (a2 + a3);

        if (sgm > m) {
            float corr = expf(m - sgm);
            ssum *= corr;
#pragma unroll
            for (int d = 0; d < DHQ; d++) o[d] *= corr;
            m = sgm;
        }
        float p = expf(sgm - m);
        ssum += p;
#pragma unroll
        for (int c = 0; c < DHQ; c += 4) {
            float4 v4 = *(const float4*)&Vt[j][c];
            o[c]     += p * v4.x;
            o[c + 1] += p * v4.y;
            o[c + 2] += p * v4.z;
            o[c + 3] += p * v4.w;
        }
    }

    const float inv = 1.f / ssum;
    float* orow = out + (size_t)(t * LQ + l) * DQ + h * DHQ;
#pragma unroll
    for (int d = 0; d < DHQ; d += 4) {
        float4 v = make_float4(o[d] * inv, o[d + 1] * inv, o[d + 2] * inv, o[d + 3] * inv);
        *(float4*)(orow + d) = v;
    }
}

// =================================================================
extern "C" void kernel_launch(void* const* d_in, const int* in_sizes, int n_in,
                              void* d_out, int out_size)
{
    const float* x     = (const float*)d_in[0];
    const float* w_row = (const float*)d_in[1];
    const float* b_row = (const float*)d_in[2];
    const float* w_col = (const float*)d_in[3];
    const float* b_col = (const float*)d_in[4];
    const float* g1    = (const float*)d_in[5];
    const float* beta1 = (const float*)d_in[6];
    const float* g2    = (const float*)d_in[7];
    const float* beta2 = (const float*)d_in[8];
    float* out = (float*)d_out;

    float *qkv, *attn, *tmp, *out1, *wsp;
    uint32_t* qksp;
    cudaGetSymbolAddress((void**)&qkv,  g_qkv);
    cudaGetSymbolAddress((void**)&attn, g_attn);
    cudaGetSymbolAddress((void**)&tmp,  g_tmp);
    cudaGetSymbolAddress((void**)&out1, g_out1);
    cudaGetSymbolAddress((void**)&wsp,  g_wsplit);
    cudaGetSymbolAddress((void**)&qksp, g_qksp);

    __nv_bfloat16* a_hi = (__nv_bfloat16*)tmp;
    __nv_bfloat16* a_lo = a_hi + (size_t)MQ * DQ;
    __nv_bfloat16* w_hi = (__nv_bfloat16*)wsp;
    __nv_bfloat16* w_lo = w_hi + (size_t)N3Q * DQ;
    __nv_bfloat16* at_hi = (__nv_bfloat16*)wsp;           // attn splits (after w consumed)
    __nv_bfloat16* at_lo = at_hi + (size_t)AT_ELE;

    cudaFuncSetAttribute(qkv_gemm_bf16,
                         cudaFuncAttributeMaxDynamicSharedMemorySize, MV2_SMEM);
    cudaFuncSetAttribute(row_logits_mma,
                         cudaFuncAttributeMaxDynamicSharedMemorySize, MV2_SMEM);
    cudaFuncSetAttribute(row_av_mma,
                         cudaFuncAttributeMaxDynamicSharedMemorySize, MV2_SMEM);
    cudaFuncSetAttribute(split_v,
                         cudaFuncAttributeMaxDynamicSharedMemorySize, 64 * 258 * 4);

    const int n4A = MQ * DQ / 4;     // 6291456
    const int n4B = N3Q * DQ / 4;    // 442368
    dim3 gemm_grid(N3Q / 128, MQ / 128);   // (18, 256)

    // --- row stage ---
    split_bf16<<<n4A / 256, 256>>>(x, a_hi, a_lo, n4A);
    split_bf16<<<n4B / 256, 256>>>(w_row, w_hi, w_lo, n4B);
    qkv_gemm_bf16<<<gemm_grid, 256, MV2_SMEM>>>(a_hi, a_lo, w_hi, w_lo, b_row, qkv);

    split_qk<<<2 * QK_U32 / 256, 256>>>(qkv, qksp);
    row_logits_mma<<<dim3(2, 2, HQ * NSP), 256, MV2_SMEM>>>(qksp, out1);
    softmax_row<<<HQ * LQ, 256>>>(out1, attn);

    split_bf16<<<(HQ * LQ * LQ / 4) / 256, 256>>>(attn, at_hi, at_lo, HQ * LQ * LQ / 4);
    split_v<<<dim3(SQ, HQ), 256, 64 * 258 * 4>>>(qkv, qksp);
    row_av_mma<<<dim3(64, 2, HQ), 256, MV2_SMEM>>>((uint32_t*)at_hi, qksp, tmp);
    add_ln_perm<<<MQ, 256>>>(x, tmp, g1, beta1, out1);

    // --- column stage ---
    split_bf16<<<n4A / 256, 256>>>(out1, a_hi, a_lo, n4A);
    split_bf16<<<n4B / 256, 256>>>(w_col, w_hi, w_lo, n4B);
    qkv_gemm_bf16<<<gemm_grid, 256, MV2_SMEM>>>(a_hi, a_lo, w_hi, w_lo, b_col, qkv);

    col_attn_kernel<<<dim3(LQ, HQ), 128>>>(qkv, tmp);
    add_ln<<<MQ, 256>>>(out1, tmp, g2, beta2, out);
}